// round 1
// baseline (speedup 1.0000x reference)
#include <cuda_runtime.h>
#include <math.h>
#include <stdint.h>

// ---------------- problem constants ----------------
#define BATCH 128
#define HDIM  512
#define TZ    64
#define TU    128
#define EDIM  512
#define DDIM  5
#define VOC   8000
#define GIN   1541          // E + 2H + D
#define NG    1536          // 3H
#define PV    8064          // V + TZ
#define SLD   16064         // V + PV  (full pre-softmax row)

// ---------------- scratch (single device buffer, offsets below) -------------
// floats:
//  preZ     65536
//  preU     65536
//  part    131072   (max 16384 rows * 8 n-blocks)
//  scoreZ    8192
//  scoreU   16384
//  scoreC    8192
//  ctxZ     65536
//  ctxU     65536
//  gin     197248
//  gi      196608
//  gh      196608
//  hnew     65536
//  gencat  196608
//  S      2056192
//  ez        8192
//  mz         128
#define OFF_PREZ   0
#define OFF_PREU   (OFF_PREZ + 65536)
#define OFF_PART   (OFF_PREU + 65536)
#define OFF_SCZ    (OFF_PART + 131072)
#define OFF_SCU    (OFF_SCZ + 8192)
#define OFF_SCC    (OFF_SCU + 16384)
#define OFF_CTXZ   (OFF_SCC + 8192)
#define OFF_CTXU   (OFF_CTXZ + 65536)
#define OFF_GIN    (OFF_CTXU + 65536)
#define OFF_GI     (OFF_GIN + 197248)
#define OFF_GH     (OFF_GI + 196608)
#define OFF_HNEW   (OFF_GH + 196608)
#define OFF_GENCAT (OFF_HNEW + 65536)
#define OFF_S      (OFF_GENCAT + 196608)
#define OFF_EZ     (OFF_S + 2056192)
#define OFF_MZ     (OFF_EZ + 8192)
#define SCRATCH_FLOATS (OFF_MZ + 128)

__device__ float g_scratch[SCRATCH_FLOATS];

// ---------------- generic NT SGEMM, optionally fused tanh + weighted reduce --
// C = A(MxK, lda) @ Bw(NxK, ldb, column offset bofs)^T  [+ bias]
// FUSED: score-partials per (row, n-block):
//   part[row * gridDim.x + bx] = sum_{col in block} tanh(acc + bias + pre[b,col]) * wvec[(b,)col]
// with b = row % Bmod.
#define BM 64
#define BN 64
#define BKK 16

template<int FUSED, int PERB>
__global__ void gemm_nt(const float* __restrict__ A, int lda,
                        const float* __restrict__ Bw, int ldb, int bofs,
                        const float* __restrict__ bias,
                        const float* __restrict__ pre,
                        const float* __restrict__ wvec,
                        float* __restrict__ C, int ldc,
                        int M, int N, int K, int Bmod)
{
    __shared__ float As[BKK][BM];
    __shared__ float Bs[BKK][BN];
    __shared__ float red[BM][16];

    const int tid = threadIdx.x;
    const int tx = tid & 15, ty = tid >> 4;
    const int row0 = blockIdx.y * BM, col0 = blockIdx.x * BN;
    const int lr = tid >> 2;            // 0..63
    const int lk = (tid & 3) * 4;       // 0,4,8,12

    float acc[4][4] = {};

    const float* Arow = A + (size_t)(row0 + lr) * lda;
    const float* Brow = Bw + (size_t)(col0 + lr) * ldb + bofs;

    for (int k0 = 0; k0 < K; k0 += BKK) {
        #pragma unroll
        for (int i = 0; i < 4; i++) {
            int kk = k0 + lk + i;
            As[lk + i][lr] = (kk < K) ? Arow[kk] : 0.f;
            Bs[lk + i][lr] = (kk < K) ? Brow[kk] : 0.f;
        }
        __syncthreads();
        #pragma unroll
        for (int k = 0; k < BKK; k++) {
            float a[4], b[4];
            #pragma unroll
            for (int i = 0; i < 4; i++) { a[i] = As[k][ty * 4 + i]; }
            #pragma unroll
            for (int j = 0; j < 4; j++) { b[j] = Bs[k][tx * 4 + j]; }
            #pragma unroll
            for (int i = 0; i < 4; i++)
                #pragma unroll
                for (int j = 0; j < 4; j++)
                    acc[i][j] = fmaf(a[i], b[j], acc[i][j]);
        }
        __syncthreads();
    }

    if (!FUSED) {
        #pragma unroll
        for (int i = 0; i < 4; i++) {
            int row = row0 + ty * 4 + i;
            #pragma unroll
            for (int j = 0; j < 4; j++) {
                int col = col0 + tx * 4 + j;
                float v = acc[i][j];
                if (bias) v += bias[col];
                C[(size_t)row * ldc + col] = v;
            }
        }
    } else {
        #pragma unroll
        for (int i = 0; i < 4; i++) {
            int row = row0 + ty * 4 + i;
            int bb = row % Bmod;
            float s = 0.f;
            #pragma unroll
            for (int j = 0; j < 4; j++) {
                int col = col0 + tx * 4 + j;
                float e = acc[i][j];
                if (bias) e += bias[col];
                if (pre)  e += pre[bb * N + col];
                e = tanhf(e);
                float wv = PERB ? wvec[bb * N + col] : wvec[col];
                s += e * wv;
            }
            red[ty * 4 + i][tx] = s;
        }
        __syncthreads();
        if (tid < BM) {
            float s = 0.f;
            #pragma unroll
            for (int g = 0; g < 16; g++) s += red[tid][g];
            C[(size_t)(row0 + tid) * gridDim.x + blockIdx.x] = s;
        }
    }
}

// sum G partials per row (deterministic, no atomics)
__global__ void reduceN(const float* __restrict__ part, float* __restrict__ out,
                        int M, int G)
{
    int m = blockIdx.x * blockDim.x + threadIdx.x;
    if (m < M) {
        float s = 0.f;
        for (int g = 0; g < G; g++) s += part[(size_t)m * G + g];
        out[m] = s;
    }
}

// per-b softmax over T scores (layout score[t*BATCH + b]) + context weighted sum
__global__ void softmax_ctx(const float* __restrict__ score,
                            const float* __restrict__ enc,   // (T,B,H)
                            float* __restrict__ ctx, int T)
{
    int b = blockIdx.x, tid = threadIdx.x;        // 256 threads
    __shared__ float sw[128];
    __shared__ float red[256];

    float v = -1e30f;
    if (tid < T) { v = score[tid * BATCH + b]; sw[tid] = v; }
    red[tid] = v;
    __syncthreads();
    for (int s = 128; s > 0; s >>= 1) { if (tid < s) red[tid] = fmaxf(red[tid], red[tid + s]); __syncthreads(); }
    float mx = red[0];
    __syncthreads();

    float e = 0.f;
    if (tid < T) { e = expf(sw[tid] - mx); }
    red[tid] = e;
    __syncthreads();
    for (int s = 128; s > 0; s >>= 1) { if (tid < s) red[tid] += red[tid + s]; __syncthreads(); }
    float inv = 1.f / red[0];
    __syncthreads();
    if (tid < T) sw[tid] = e * inv;
    __syncthreads();

    for (int h = tid; h < HDIM; h += 256) {
        float acc = 0.f;
        for (int t = 0; t < T; t++)
            acc += sw[t] * enc[((size_t)t * BATCH + b) * HDIM + h];
        ctx[b * HDIM + h] = acc;
    }
}

// copy-score: per-b max + exp (unnormalized)
__global__ void copy_exp(const float* __restrict__ score,
                         float* __restrict__ ez, float* __restrict__ mz)
{
    int b = blockIdx.x, t = threadIdx.x;          // 64 threads
    __shared__ float sv[64];
    __shared__ float red[64];
    float v = score[t * BATCH + b];
    sv[t] = v; red[t] = v;
    __syncthreads();
    for (int s = 32; s > 0; s >>= 1) { if (t < s) red[t] = fmaxf(red[t], red[t + s]); __syncthreads(); }
    float mx = red[0];
    ez[b * TZ + t] = expf(sv[t] - mx);
    if (t == 0) mz[b] = mx;
}

// z_copy = log(sum_t e[b,t] * sparse[b,t,v]) + m[b], written into S cols [VOC, VOC+PV)
__global__ void zcopy_kernel(const float* __restrict__ sp,
                             const float* __restrict__ ez,
                             const float* __restrict__ mz,
                             float* __restrict__ S)
{
    int b = blockIdx.y;
    int v = blockIdx.x * blockDim.x + threadIdx.x;
    __shared__ float e[TZ];
    if (threadIdx.x < TZ) e[threadIdx.x] = ez[b * TZ + threadIdx.x];
    __syncthreads();
    if (v < PV) {
        const float* row = sp + (size_t)b * TZ * PV + v;
        float acc = 0.f;
        #pragma unroll 8
        for (int t = 0; t < TZ; t++) acc += e[t] * row[(size_t)t * PV];
        S[(size_t)b * SLD + VOC + v] = logf(acc) + mz[b];
    }
}

// gin = [m_embed(512) | u_ctx(512) | z_ctx(512) | degree(5)]
__global__ void build_gin(const int* __restrict__ mt, const float* __restrict__ emb,
                          const float* __restrict__ ctxU, const float* __restrict__ ctxZ,
                          const float* __restrict__ degree, float* __restrict__ gin)
{
    int b = blockIdx.x;
    int m = mt[b];
    for (int i = threadIdx.x; i < GIN; i += blockDim.x) {
        float v;
        if (i < 512)       v = emb[(size_t)m * EDIM + i];
        else if (i < 1024) v = ctxU[b * HDIM + (i - 512)];
        else if (i < 1536) v = ctxZ[b * HDIM + (i - 1024)];
        else               v = degree[b * DDIM + (i - 1536)];
        gin[(size_t)b * GIN + i] = v;
    }
}

// GRU gates -> h_new; also assemble gencat = [z_ctx | u_ctx | h_new]
__global__ void gru_gate(const float* __restrict__ gi, const float* __restrict__ gh,
                         const float* __restrict__ hprev,
                         const float* __restrict__ ctxZ, const float* __restrict__ ctxU,
                         float* __restrict__ hnew, float* __restrict__ gencat)
{
    int idx = blockIdx.x * blockDim.x + threadIdx.x;
    if (idx >= BATCH * HDIM) return;
    int b = idx >> 9, j = idx & 511;
    const float* gib = gi + (size_t)b * NG;
    const float* ghb = gh + (size_t)b * NG;
    float r = 1.f / (1.f + expf(-(gib[j]        + ghb[j])));
    float z = 1.f / (1.f + expf(-(gib[512 + j]  + ghb[512 + j])));
    float n = tanhf(gib[1024 + j] + r * ghb[1024 + j]);
    float h = (1.f - z) * n + z * hprev[idx];
    hnew[idx] = h;
    gencat[(size_t)b * NG + j]         = ctxZ[idx];
    gencat[(size_t)b * NG + 512 + j]   = ctxU[idx];
    gencat[(size_t)b * NG + 1024 + j]  = h;
}

// final softmax over SLD, then proba = [gen + cp[:, :V] | cp[:, V:]]
__global__ void final_softmax(const float* __restrict__ S, float* __restrict__ out)
{
    int b = blockIdx.x, tid = threadIdx.x;
    __shared__ float red[256];
    const float* row = S + (size_t)b * SLD;

    float mx = -1e30f;
    for (int i = tid; i < SLD; i += 256) mx = fmaxf(mx, row[i]);
    red[tid] = mx;
    __syncthreads();
    for (int s = 128; s > 0; s >>= 1) { if (tid < s) red[tid] = fmaxf(red[tid], red[tid + s]); __syncthreads(); }
    mx = red[0];
    __syncthreads();

    float sm = 0.f;
    for (int i = tid; i < SLD; i += 256) sm += expf(row[i] - mx);
    red[tid] = sm;
    __syncthreads();
    for (int s = 128; s > 0; s >>= 1) { if (tid < s) red[tid] += red[tid + s]; __syncthreads(); }
    float inv = 1.f / red[0];

    for (int v = tid; v < PV; v += 256) {
        float cp = expf(row[VOC + v] - mx) * inv;
        float o = (v < VOC) ? expf(row[v] - mx) * inv + cp : cp;
        out[(size_t)b * PV + v] = o;
    }
}

__global__ void write_gru_out(const float* __restrict__ hnew, float* __restrict__ out,
                              int out_size)
{
    int i = blockIdx.x * blockDim.x + threadIdx.x;
    if (i >= BATCH * HDIM) return;
    const int base = BATCH * PV;
    if (out_size >= base + BATCH * HDIM)     out[base + i] = hnew[i];
    if (out_size >= base + 2 * BATCH * HDIM) out[base + BATCH * HDIM + i] = hnew[i];
}

// ---------------------------------------------------------------------------
extern "C" void kernel_launch(void* const* d_in, const int* in_sizes, int n_in,
                              void* d_out, int out_size)
{
    const float* z_enc  = (const float*)d_in[0];   // (64,128,512)
    const float* u_enc  = (const float*)d_in[1];   // (128,128,512)
    const int*   mt     = (const int*)d_in[2];     // (1,128)
    const float* degree = (const float*)d_in[3];   // (128,5)
    const float* hid    = (const float*)d_in[4];   // (1,128,512)
    const float* sp     = (const float*)d_in[5];   // (128,64,8064)
    const float* emb    = (const float*)d_in[6];   // (8000,512)
    const float* azW    = (const float*)d_in[7];   // (512,1024)
    const float* azb    = (const float*)d_in[8];
    const float* azv    = (const float*)d_in[9];
    const float* auW    = (const float*)d_in[10];
    const float* aub    = (const float*)d_in[11];
    const float* auv    = (const float*)d_in[12];
    const float* Wih    = (const float*)d_in[13];  // (1536,1541)
    const float* Whh    = (const float*)d_in[14];  // (1536,512)
    const float* bih    = (const float*)d_in[15];
    const float* bhh    = (const float*)d_in[16];
    const float* pW     = (const float*)d_in[17];  // (8000,1536)
    const float* pb     = (const float*)d_in[18];
    const float* c2W    = (const float*)d_in[19];  // (512,512)
    const float* c2b    = (const float*)d_in[20];
    float* out = (float*)d_out;

    float* base = nullptr;
    cudaGetSymbolAddress((void**)&base, g_scratch);
    float* preZ   = base + OFF_PREZ;
    float* preU   = base + OFF_PREU;
    float* part   = base + OFF_PART;
    float* scoreZ = base + OFF_SCZ;
    float* scoreU = base + OFF_SCU;
    float* scoreC = base + OFF_SCC;
    float* ctxZ   = base + OFF_CTXZ;
    float* ctxU   = base + OFF_CTXU;
    float* gin    = base + OFF_GIN;
    float* gi     = base + OFF_GI;
    float* gh     = base + OFF_GH;
    float* hnew   = base + OFF_HNEW;
    float* gencat = base + OFF_GENCAT;
    float* S      = base + OFF_S;
    float* ez     = base + OFF_EZ;
    float* mz     = base + OFF_MZ;

    // 1) hidden projections (include attn biases): pre = hid @ W[:, :H]^T + b
    gemm_nt<0,0><<<dim3(HDIM/BN, BATCH/BM), 256>>>(hid, HDIM, azW, 2*HDIM, 0, azb,
                                                   nullptr, nullptr, preZ, HDIM,
                                                   BATCH, HDIM, HDIM, BATCH);
    gemm_nt<0,0><<<dim3(HDIM/BN, BATCH/BM), 256>>>(hid, HDIM, auW, 2*HDIM, 0, aub,
                                                   nullptr, nullptr, preU, HDIM,
                                                   BATCH, HDIM, HDIM, BATCH);

    // 2) fused attention energy+score GEMMs
    gemm_nt<1,0><<<dim3(HDIM/BN, (TZ*BATCH)/BM), 256>>>(z_enc, HDIM, azW, 2*HDIM, HDIM,
                                                        nullptr, preZ, azv, part, 0,
                                                        TZ*BATCH, HDIM, HDIM, BATCH);
    reduceN<<<(TZ*BATCH)/256, 256>>>(part, scoreZ, TZ*BATCH, HDIM/BN);

    gemm_nt<1,0><<<dim3(HDIM/BN, (TU*BATCH)/BM), 256>>>(u_enc, HDIM, auW, 2*HDIM, HDIM,
                                                        nullptr, preU, auv, part, 0,
                                                        TU*BATCH, HDIM, HDIM, BATCH);
    reduceN<<<(TU*BATCH)/256, 256>>>(part, scoreU, TU*BATCH, HDIM/BN);

    // 3) softmax + context
    softmax_ctx<<<BATCH, 256>>>(scoreZ, z_enc, ctxZ, TZ);
    softmax_ctx<<<BATCH, 256>>>(scoreU, u_enc, ctxU, TU);

    // 4) GRU
    build_gin<<<BATCH, 256>>>(mt, emb, ctxU, ctxZ, degree, gin);
    gemm_nt<0,0><<<dim3(NG/BN, BATCH/BM), 256>>>(gin, GIN, Wih, GIN, 0, bih,
                                                 nullptr, nullptr, gi, NG,
                                                 BATCH, NG, GIN, BATCH);
    gemm_nt<0,0><<<dim3(NG/BN, BATCH/BM), 256>>>(hid, HDIM, Whh, HDIM, 0, bhh,
                                                 nullptr, nullptr, gh, NG,
                                                 BATCH, NG, HDIM, BATCH);
    gru_gate<<<(BATCH*HDIM)/256, 256>>>(gi, gh, hid, ctxZ, ctxU, hnew, gencat);

    // 5) copy-score GEMM (fused tanh + per-b h_new reduce)
    gemm_nt<1,1><<<dim3(HDIM/BN, (TZ*BATCH)/BM), 256>>>(z_enc, HDIM, c2W, HDIM, 0,
                                                        c2b, nullptr, hnew, part, 0,
                                                        TZ*BATCH, HDIM, HDIM, BATCH);
    reduceN<<<(TZ*BATCH)/256, 256>>>(part, scoreC, TZ*BATCH, HDIM/BN);

    // 6) projection -> S[:, :V]
    gemm_nt<0,0><<<dim3(VOC/BN, BATCH/BM), 256>>>(gencat, NG, pW, NG, 0, pb,
                                                  nullptr, nullptr, S, SLD,
                                                  BATCH, VOC, NG, BATCH);

    // 7) copy distribution -> S[:, V:]
    copy_exp<<<BATCH, TZ>>>(scoreC, ez, mz);
    zcopy_kernel<<<dim3((PV + 255)/256, BATCH), 256>>>(sp, ez, mz, S);

    // 8) final softmax + combine -> proba, plus gru_out x2
    final_softmax<<<BATCH, 256>>>(S, out);
    write_gru_out<<<(BATCH*HDIM)/256, 256>>>(hnew, out, out_size);
}

// round 4
// speedup vs baseline: 2.9305x; 2.9305x over previous
#include <cuda_runtime.h>
#include <math.h>
#include <stdint.h>

// ---------------- problem constants ----------------
#define BATCH 128
#define HDIM  512
#define TZ    64
#define TU    128
#define DDIM  5
#define VOC   8000
#define GINR  1541          // real gin width
#define GINP  1552          // padded to multiple of 16
#define NG    1536          // 3H
#define PV    8064          // V + TZ
#define SLD   16064         // V + PV

// ---------------- scratch offsets (floats) ----------------
#define OFF_PREZ   0
#define OFF_PREU   (OFF_PREZ + 65536)
#define OFF_PART   (OFF_PREU + 65536)          // 2,048,000 floats max
#define OFF_SCZ    (OFF_PART + 2048000)
#define OFF_SCU    (OFF_SCZ + 8192)
#define OFF_SCC    (OFF_SCU + 16384)
#define OFF_CTXZ   (OFF_SCC + 8192)
#define OFF_CTXU   (OFF_CTXZ + 65536)
#define OFF_GIN    (OFF_CTXU + 65536)          // 128*1552
#define OFF_GI     (OFF_GIN + 198656)
#define OFF_GH     (OFF_GI + 196608)
#define OFF_HNEW   (OFF_GH + 196608)
#define OFF_GENCAT (OFF_HNEW + 65536)
#define OFF_S      (OFF_GENCAT + 196608)       // 128*16064
#define OFF_EZ     (OFF_S + 2056192)
#define OFF_MZ     (OFF_EZ + 8192)
#define OFF_WIHP   (OFF_MZ + 128)              // 1536*1552
#define SCRATCH_FLOATS (OFF_WIHP + 2383872)

__device__ float g_scratch[SCRATCH_FLOATS];

// ---------------- helpers ----------------
__device__ __forceinline__ uint32_t f2tf32(float f) {
    uint32_t r;
    asm("cvt.rna.tf32.f32 %0, %1;" : "=r"(r) : "f"(f));
    return r;
}

__device__ __forceinline__ void mma_tf32(float* c, const uint32_t* a,
                                         uint32_t b0, uint32_t b1) {
    asm volatile(
        "mma.sync.aligned.m16n8k8.row.col.f32.tf32.tf32.f32 "
        "{%0,%1,%2,%3}, {%4,%5,%6,%7}, {%8,%9}, {%0,%1,%2,%3};"
        : "+f"(c[0]), "+f"(c[1]), "+f"(c[2]), "+f"(c[3])
        : "r"(a[0]), "r"(a[1]), "r"(a[2]), "r"(a[3]), "r"(b0), "r"(b1));
}

// ---------------- TF32 NT GEMM ----------------
// C = A(MxK, lda) @ Bw(NxK, ldb, +bofs)^T
// Plain (FUSED=0): splitK via gridDim.z; slice z writes part at C + z*M*ldc (no bias).
// Fused (FUSED=1): per (row, n-block) partial of sum_col tanh(acc + bias + pre[b,col]) * wv
//                  with b = row % BATCH; wv = PERB ? wvec[b*N+col] : wvec[col].
#define BM 128
#define BN 128
#define BK 16
#define PAD 20

template<int FUSED, int PERB>
__global__ void __launch_bounds__(256, 2)
gemm_tf32(const float* __restrict__ A, int lda,
          const float* __restrict__ Bw, int ldb, int bofs,
          const float* __restrict__ bias,
          const float* __restrict__ pre,
          const float* __restrict__ wvec,
          float* __restrict__ C, int ldc,
          int M, int N, int K)
{
    __shared__ __align__(16) uint32_t As[2][BM][PAD];
    __shared__ __align__(16) uint32_t Bs[2][BN][PAD];
    __shared__ float red[BM][2];

    const int tid = threadIdx.x;
    const int lane = tid & 31, wid = tid >> 5;
    const int warpRow = wid & 3, warpCol = wid >> 2;
    const int row0 = blockIdx.y * BM, col0 = blockIdx.x * BN;

    const int nkTot = K / BK;
    const int nz = gridDim.z;
    const int kPer = (nkTot + nz - 1) / nz;
    const int kt0 = blockIdx.z * kPer;
    int kt1 = kt0 + kPer; if (kt1 > nkTot) kt1 = nkTot;

    float acc[2][8][4];
    #pragma unroll
    for (int i = 0; i < 2; i++)
        #pragma unroll
        for (int j = 0; j < 8; j++)
            #pragma unroll
            for (int l = 0; l < 4; l++) acc[i][j][l] = 0.f;

    float4 ra[2], rb[2];

    auto gload = [&](int kt) {
        const int kbase = kt * BK;
        #pragma unroll
        for (int h = 0; h < 2; h++) {
            int idx = tid + h * 256;
            int r = idx >> 2, kq = (idx & 3) << 2;
            ra[h] = *(const float4*)(A + (size_t)(row0 + r) * lda + kbase + kq);
            int cn = col0 + r;
            if (cn < N)
                rb[h] = *(const float4*)(Bw + (size_t)cn * ldb + bofs + kbase + kq);
            else
                rb[h] = make_float4(0.f, 0.f, 0.f, 0.f);
        }
    };
    auto sstore = [&](int buf) {
        #pragma unroll
        for (int h = 0; h < 2; h++) {
            int idx = tid + h * 256;
            int r = idx >> 2, kq = (idx & 3) << 2;
            uint4 ua, ub;
            ua.x = f2tf32(ra[h].x); ua.y = f2tf32(ra[h].y);
            ua.z = f2tf32(ra[h].z); ua.w = f2tf32(ra[h].w);
            ub.x = f2tf32(rb[h].x); ub.y = f2tf32(rb[h].y);
            ub.z = f2tf32(rb[h].z); ub.w = f2tf32(rb[h].w);
            *(uint4*)&As[buf][r][kq] = ua;
            *(uint4*)&Bs[buf][r][kq] = ub;
        }
    };

    gload(kt0);
    sstore(0);
    __syncthreads();

    int buf = 0;
    for (int kt = kt0; kt < kt1; kt++) {
        if (kt + 1 < kt1) gload(kt + 1);

        #pragma unroll
        for (int ks = 0; ks < 2; ks++) {
            const int k = ks * 8 + (lane & 3);
            uint32_t a[2][4];
            #pragma unroll
            for (int mi = 0; mi < 2; mi++) {
                int r = warpRow * 32 + mi * 16 + (lane >> 2);
                a[mi][0] = As[buf][r][k];
                a[mi][1] = As[buf][r + 8][k];
                a[mi][2] = As[buf][r][k + 4];
                a[mi][3] = As[buf][r + 8][k + 4];
            }
            #pragma unroll
            for (int ni = 0; ni < 8; ni++) {
                int cb = warpCol * 64 + ni * 8 + (lane >> 2);
                uint32_t b0 = Bs[buf][cb][k];
                uint32_t b1 = Bs[buf][cb][k + 4];
                #pragma unroll
                for (int mi = 0; mi < 2; mi++)
                    mma_tf32(acc[mi][ni], a[mi], b0, b1);
            }
        }

        if (kt + 1 < kt1) sstore(buf ^ 1);
        __syncthreads();
        buf ^= 1;
    }

    if (!FUSED) {
        float* Cb = C + (size_t)blockIdx.z * ((size_t)M * ldc);
        #pragma unroll
        for (int mi = 0; mi < 2; mi++) {
            int r = row0 + warpRow * 32 + mi * 16 + (lane >> 2);
            #pragma unroll
            for (int ni = 0; ni < 8; ni++) {
                int cb = col0 + warpCol * 64 + ni * 8 + 2 * (lane & 3);
                if (cb < N)     Cb[(size_t)r * ldc + cb]           = acc[mi][ni][0];
                if (cb + 1 < N) Cb[(size_t)r * ldc + cb + 1]       = acc[mi][ni][1];
                if (cb < N)     Cb[(size_t)(r + 8) * ldc + cb]     = acc[mi][ni][2];
                if (cb + 1 < N) Cb[(size_t)(r + 8) * ldc + cb + 1] = acc[mi][ni][3];
            }
        }
    } else {
        #pragma unroll
        for (int mi = 0; mi < 2; mi++) {
            int rl = warpRow * 32 + mi * 16 + (lane >> 2);   // local row
            int bL = rl, bH = rl + 8;                        // b = row % 128
            float s0 = 0.f, s1 = 0.f;
            #pragma unroll
            for (int ni = 0; ni < 8; ni++) {
                int colL = warpCol * 64 + ni * 8 + 2 * (lane & 3);
                #pragma unroll
                for (int j = 0; j < 2; j++) {
                    int gc = col0 + colL + j;
                    float bs = bias ? bias[gc] : 0.f;
                    float e0 = acc[mi][ni][j]     + bs;
                    float e1 = acc[mi][ni][2 + j] + bs;
                    if (pre) { e0 += pre[bL * N + gc]; e1 += pre[bH * N + gc]; }
                    e0 = tanhf(e0); e1 = tanhf(e1);
                    float w0 = PERB ? wvec[bL * N + gc] : wvec[gc];
                    float w1 = PERB ? wvec[bH * N + gc] : wvec[gc];
                    s0 += e0 * w0;
                    s1 += e1 * w1;
                }
            }
            s0 += __shfl_xor_sync(0xffffffffu, s0, 1);
            s0 += __shfl_xor_sync(0xffffffffu, s0, 2);
            s1 += __shfl_xor_sync(0xffffffffu, s1, 1);
            s1 += __shfl_xor_sync(0xffffffffu, s1, 2);
            if ((lane & 3) == 0) {
                red[rl][warpCol]     = s0;
                red[rl + 8][warpCol] = s1;
            }
        }
        __syncthreads();
        if (tid < BM) {
            float s = red[tid][0] + red[tid][1];
            C[(size_t)(row0 + tid) * gridDim.x + blockIdx.x] = s;
        }
    }
}

// sum split-K slices + bias -> dst (row-major with stride ldd)
__global__ void reduceK(const float* __restrict__ part, int slices, int M, int N,
                        const float* __restrict__ bias, float* __restrict__ dst, int ldd)
{
    int i = blockIdx.x * blockDim.x + threadIdx.x;
    if (i >= M * N) return;
    int m = i / N, n = i - m * N;
    float s = bias ? bias[n] : 0.f;
    for (int z = 0; z < slices; z++) s += part[(size_t)z * M * N + i];
    dst[(size_t)m * ldd + n] = s;
}

// sum G n-block partials per row (fused-score reduce)
__global__ void reduceN(const float* __restrict__ part, float* __restrict__ out,
                        int M, int G)
{
    int m = blockIdx.x * blockDim.x + threadIdx.x;
    if (m < M) {
        float s = 0.f;
        for (int g = 0; g < G; g++) s += part[(size_t)m * G + g];
        out[m] = s;
    }
}

// pad-copy Wih (1536 x 1541) -> (1536 x 1552), zero-filled tail
__global__ void padWih(const float* __restrict__ W, float* __restrict__ Wp)
{
    int i = blockIdx.x * blockDim.x + threadIdx.x;
    if (i >= NG * GINP) return;
    int n = i / GINP, k = i - n * GINP;
    Wp[i] = (k < GINR) ? W[(size_t)n * GINR + k] : 0.f;
}

// per-b softmax over T scores (score[t*BATCH + b]) + context weighted sum
__global__ void softmax_ctx(const float* __restrict__ score,
                            const float* __restrict__ enc,   // (T,B,H)
                            float* __restrict__ ctx, int T)
{
    int b = blockIdx.x, tid = threadIdx.x;        // 256 threads
    __shared__ float sw[128];
    __shared__ float red[256];

    float v = -1e30f;
    if (tid < T) { v = score[tid * BATCH + b]; sw[tid] = v; }
    red[tid] = v;
    __syncthreads();
    for (int s = 128; s > 0; s >>= 1) { if (tid < s) red[tid] = fmaxf(red[tid], red[tid + s]); __syncthreads(); }
    float mx = red[0];
    __syncthreads();

    float e = 0.f;
    if (tid < T) e = expf(sw[tid] - mx);
    red[tid] = e;
    __syncthreads();
    for (int s = 128; s > 0; s >>= 1) { if (tid < s) red[tid] += red[tid + s]; __syncthreads(); }
    float inv = 1.f / red[0];
    __syncthreads();
    if (tid < T) sw[tid] = e * inv;
    __syncthreads();

    for (int h = tid; h < HDIM; h += 256) {
        float acc = 0.f;
        for (int t = 0; t < T; t++)
            acc += sw[t] * enc[((size_t)t * BATCH + b) * HDIM + h];
        ctx[b * HDIM + h] = acc;
    }
}

// copy-score: per-b max + exp (unnormalized)
__global__ void copy_exp(const float* __restrict__ score,
                         float* __restrict__ ez, float* __restrict__ mz)
{
    int b = blockIdx.x, t = threadIdx.x;          // 64 threads
    __shared__ float sv[64];
    __shared__ float red[64];
    float v = score[t * BATCH + b];
    sv[t] = v; red[t] = v;
    __syncthreads();
    for (int s = 32; s > 0; s >>= 1) { if (t < s) red[t] = fmaxf(red[t], red[t + s]); __syncthreads(); }
    float mx = red[0];
    ez[b * TZ + t] = expf(sv[t] - mx);
    if (t == 0) mz[b] = mx;
}

// z_copy = log(sum_t e[b,t] * sparse[b,t,v]) + m[b] -> S cols [VOC, VOC+PV)
__global__ void zcopy_kernel(const float* __restrict__ sp,
                             const float* __restrict__ ez,
                             const float* __restrict__ mz,
                             float* __restrict__ S)
{
    int b = blockIdx.y;
    int v = blockIdx.x * blockDim.x + threadIdx.x;
    __shared__ float e[TZ];
    if (threadIdx.x < TZ) e[threadIdx.x] = ez[b * TZ + threadIdx.x];
    __syncthreads();
    if (v < PV) {
        const float* row = sp + (size_t)b * TZ * PV + v;
        float acc = 0.f;
        #pragma unroll 8
        for (int t = 0; t < TZ; t++) acc += e[t] * row[(size_t)t * PV];
        S[(size_t)b * SLD + VOC + v] = logf(acc) + mz[b];
    }
}

// gin = [m_embed(512) | u_ctx(512) | z_ctx(512) | degree(5) | zero pad]
__global__ void build_gin(const int* __restrict__ mt, const float* __restrict__ emb,
                          const float* __restrict__ ctxU, const float* __restrict__ ctxZ,
                          const float* __restrict__ degree, float* __restrict__ gin)
{
    int b = blockIdx.x;
    int m = mt[b];
    for (int i = threadIdx.x; i < GINP; i += blockDim.x) {
        float v;
        if (i < 512)       v = emb[(size_t)m * 512 + i];
        else if (i < 1024) v = ctxU[b * HDIM + (i - 512)];
        else if (i < 1536) v = ctxZ[b * HDIM + (i - 1024)];
        else if (i < GINR) v = degree[b * DDIM + (i - 1536)];
        else               v = 0.f;
        gin[(size_t)b * GINP + i] = v;
    }
}

// GRU gates -> h_new; also assemble gencat = [z_ctx | u_ctx | h_new]
__global__ void gru_gate(const float* __restrict__ gi, const float* __restrict__ gh,
                         const float* __restrict__ hprev,
                         const float* __restrict__ ctxZ, const float* __restrict__ ctxU,
                         float* __restrict__ hnew, float* __restrict__ gencat)
{
    int idx = blockIdx.x * blockDim.x + threadIdx.x;
    if (idx >= BATCH * HDIM) return;
    int b = idx >> 9, j = idx & 511;
    const float* gib = gi + (size_t)b * NG;
    const float* ghb = gh + (size_t)b * NG;
    float r = 1.f / (1.f + expf(-(gib[j]        + ghb[j])));
    float z = 1.f / (1.f + expf(-(gib[512 + j]  + ghb[512 + j])));
    float n = tanhf(gib[1024 + j] + r * ghb[1024 + j]);
    float h = (1.f - z) * n + z * hprev[idx];
    hnew[idx] = h;
    gencat[(size_t)b * NG + j]        = ctxZ[idx];
    gencat[(size_t)b * NG + 512 + j]  = ctxU[idx];
    gencat[(size_t)b * NG + 1024 + j] = h;
}

// final softmax over SLD -> proba = [gen + cp[:, :V] | cp[:, V:]]
__global__ void final_softmax(const float* __restrict__ S, float* __restrict__ out)
{
    int b = blockIdx.x, tid = threadIdx.x;
    __shared__ float red[256];
    const float* row = S + (size_t)b * SLD;

    float mx = -1e30f;
    for (int i = tid; i < SLD; i += 256) mx = fmaxf(mx, row[i]);
    red[tid] = mx;
    __syncthreads();
    for (int s = 128; s > 0; s >>= 1) { if (tid < s) red[tid] = fmaxf(red[tid], red[tid + s]); __syncthreads(); }
    mx = red[0];
    __syncthreads();

    float sm = 0.f;
    for (int i = tid; i < SLD; i += 256) sm += expf(row[i] - mx);
    red[tid] = sm;
    __syncthreads();
    for (int s = 128; s > 0; s >>= 1) { if (tid < s) red[tid] += red[tid + s]; __syncthreads(); }
    float inv = 1.f / red[0];

    for (int v = tid; v < PV; v += 256) {
        float cp = expf(row[VOC + v] - mx) * inv;
        float o = (v < VOC) ? expf(row[v] - mx) * inv + cp : cp;
        out[(size_t)b * PV + v] = o;
    }
}

__global__ void write_gru_out(const float* __restrict__ hnew, float* __restrict__ out,
                              int out_size)
{
    int i = blockIdx.x * blockDim.x + threadIdx.x;
    if (i >= BATCH * HDIM) return;
    const int base = BATCH * PV;
    if (out_size >= base + BATCH * HDIM)     out[base + i] = hnew[i];
    if (out_size >= base + 2 * BATCH * HDIM) out[base + BATCH * HDIM + i] = hnew[i];
}

// ---------------------------------------------------------------------------
extern "C" void kernel_launch(void* const* d_in, const int* in_sizes, int n_in,
                              void* d_out, int out_size)
{
    const float* z_enc  = (const float*)d_in[0];   // (64,128,512)
    const float* u_enc  = (const float*)d_in[1];   // (128,128,512)
    const int*   mt     = (const int*)d_in[2];     // (1,128)
    const float* degree = (const float*)d_in[3];   // (128,5)
    const float* hid    = (const float*)d_in[4];   // (1,128,512)
    const float* sp     = (const float*)d_in[5];   // (128,64,8064)
    const float* emb    = (const float*)d_in[6];   // (8000,512)
    const float* azW    = (const float*)d_in[7];   // (512,1024)
    const float* azb    = (const float*)d_in[8];
    const float* azv    = (const float*)d_in[9];
    const float* auW    = (const float*)d_in[10];
    const float* aub    = (const float*)d_in[11];
    const float* auv    = (const float*)d_in[12];
    const float* Wih    = (const float*)d_in[13];  // (1536,1541)
    const float* Whh    = (const float*)d_in[14];  // (1536,512)
    const float* bih    = (const float*)d_in[15];
    const float* bhh    = (const float*)d_in[16];
    const float* pW     = (const float*)d_in[17];  // (8000,1536)
    const float* pb     = (const float*)d_in[18];
    const float* c2W    = (const float*)d_in[19];  // (512,512)
    const float* c2b    = (const float*)d_in[20];
    float* out = (float*)d_out;

    float* base = nullptr;
    cudaGetSymbolAddress((void**)&base, g_scratch);
    float* preZ   = base + OFF_PREZ;
    float* preU   = base + OFF_PREU;
    float* part   = base + OFF_PART;
    float* scoreZ = base + OFF_SCZ;
    float* scoreU = base + OFF_SCU;
    float* scoreC = base + OFF_SCC;
    float* ctxZ   = base + OFF_CTXZ;
    float* ctxU   = base + OFF_CTXU;
    float* gin    = base + OFF_GIN;
    float* gi     = base + OFF_GI;
    float* gh     = base + OFF_GH;
    float* hnew   = base + OFF_HNEW;
    float* gencat = base + OFF_GENCAT;
    float* S      = base + OFF_S;
    float* ez     = base + OFF_EZ;
    float* mz     = base + OFF_MZ;
    float* Wihp   = base + OFF_WIHP;

    // 0) pad Wih into aligned scratch (needed for float4 loads, K mult of 16)
    padWih<<<(NG * GINP + 255) / 256, 256>>>(Wih, Wihp);

    // 1) hidden projections: pre = hid @ W[:, :H]^T + b   (splitK=4)
    gemm_tf32<0,0><<<dim3(4, 1, 4), 256>>>(hid, HDIM, azW, 2*HDIM, 0,
                                           nullptr, nullptr, nullptr,
                                           part, HDIM, BATCH, HDIM, HDIM);
    reduceK<<<(BATCH * HDIM + 255) / 256, 256>>>(part, 4, BATCH, HDIM, azb, preZ, HDIM);
    gemm_tf32<0,0><<<dim3(4, 1, 4), 256>>>(hid, HDIM, auW, 2*HDIM, 0,
                                           nullptr, nullptr, nullptr,
                                           part, HDIM, BATCH, HDIM, HDIM);
    reduceK<<<(BATCH * HDIM + 255) / 256, 256>>>(part, 4, BATCH, HDIM, aub, preU, HDIM);

    // 2) fused attention energy+score GEMMs
    gemm_tf32<1,0><<<dim3(4, 64, 1), 256>>>(z_enc, HDIM, azW, 2*HDIM, HDIM,
                                            nullptr, preZ, azv,
                                            part, 0, TZ*BATCH, HDIM, HDIM);
    reduceN<<<(TZ * BATCH) / 256, 256>>>(part, scoreZ, TZ * BATCH, 4);

    gemm_tf32<1,0><<<dim3(4, 128, 1), 256>>>(u_enc, HDIM, auW, 2*HDIM, HDIM,
                                             nullptr, preU, auv,
                                             part, 0, TU*BATCH, HDIM, HDIM);
    reduceN<<<(TU * BATCH) / 256, 256>>>(part, scoreU, TU * BATCH, 4);

    // 3) softmax + context
    softmax_ctx<<<BATCH, 256>>>(scoreZ, z_enc, ctxZ, TZ);
    softmax_ctx<<<BATCH, 256>>>(scoreU, u_enc, ctxU, TU);

    // 4) GRU
    build_gin<<<BATCH, 256>>>(mt, emb, ctxU, ctxZ, degree, gin);
    gemm_tf32<0,0><<<dim3(12, 1, 4), 256>>>(gin, GINP, Wihp, GINP, 0,
                                            nullptr, nullptr, nullptr,
                                            part, NG, BATCH, NG, GINP);
    reduceK<<<(BATCH * NG + 255) / 256, 256>>>(part, 4, BATCH, NG, bih, gi, NG);
    gemm_tf32<0,0><<<dim3(12, 1, 2), 256>>>(hid, HDIM, Whh, HDIM, 0,
                                            nullptr, nullptr, nullptr,
                                            part, NG, BATCH, NG, HDIM);
    reduceK<<<(BATCH * NG + 255) / 256, 256>>>(part, 2, BATCH, NG, bhh, gh, NG);
    gru_gate<<<(BATCH * HDIM) / 256, 256>>>(gi, gh, hid, ctxZ, ctxU, hnew, gencat);

    // 5) copy-score GEMM (fused tanh + per-b h_new reduce)
    gemm_tf32<1,1><<<dim3(4, 64, 1), 256>>>(z_enc, HDIM, c2W, HDIM, 0,
                                            c2b, nullptr, hnew,
                                            part, 0, TZ*BATCH, HDIM, HDIM);
    reduceN<<<(TZ * BATCH) / 256, 256>>>(part, scoreC, TZ * BATCH, 4);

    // 6) projection -> S[:, :V]   (splitK=2)
    gemm_tf32<0,0><<<dim3(63, 1, 2), 256>>>(gencat, NG, pW, NG, 0,
                                            nullptr, nullptr, nullptr,
                                            part, VOC, BATCH, VOC, NG);
    reduceK<<<(BATCH * VOC + 255) / 256, 256>>>(part, 2, BATCH, VOC, pb, S, SLD);

    // 7) copy distribution -> S[:, V:]
    copy_exp<<<BATCH, TZ>>>(scoreC, ez, mz);
    zcopy_kernel<<<dim3((PV + 255) / 256, BATCH), 256>>>(sp, ez, mz, S);

    // 8) final softmax + combine -> proba, plus gru_out x2
    final_softmax<<<BATCH, 256>>>(S, out);
    write_gru_out<<<(BATCH * HDIM) / 256, 256>>>(hnew, out, out_size);
}

// round 5
// speedup vs baseline: 3.2405x; 1.1058x over previous
#include <cuda_runtime.h>
#include <math.h>
#include <stdint.h>

// ---------------- problem constants ----------------
#define BATCH 128
#define HDIM  512
#define TZ    64
#define TU    128
#define DDIM  5
#define VOC   8000
#define GINR  1541          // real gin width
#define GINP  1552          // padded to multiple of 16
#define NG    1536          // 3H
#define PV    8064          // V + TZ
#define SLD   16064         // V + PV

// ---------------- scratch offsets (floats) ----------------
#define OFF_PREZ   0
#define OFF_PREU   (OFF_PREZ + 65536)
#define OFF_PARTZ  (OFF_PREU + 65536)          // 8192*4 attn-z fused partials
#define OFF_PARTU  (OFF_PARTZ + 32768)         // 16384*4
#define OFF_PARTC  (OFF_PARTU + 65536)         // 8192*4 copy-score partials
#define OFF_PARTGI (OFF_PARTC + 32768)         // 4*128*1536
#define OFF_PARTPJ (OFF_PARTGI + 786432)       // 4*128*8000
#define OFF_SCZ    (OFF_PARTPJ + 4096000)
#define OFF_SCU    (OFF_SCZ + 8192)
#define OFF_SCC    (OFF_SCU + 16384)
#define OFF_CTXZ   (OFF_SCC + 8192)
#define OFF_CTXU   (OFF_CTXZ + 65536)
#define OFF_GIN    (OFF_CTXU + 65536)          // 128*1552
#define OFF_GI     (OFF_GIN + 198656)
#define OFF_GH     (OFF_GI + 196608)
#define OFF_HNEW   (OFF_GH + 196608)
#define OFF_GENCAT (OFF_HNEW + 65536)
#define OFF_S      (OFF_GENCAT + 196608)       // 128*16064
#define OFF_EZ     (OFF_S + 2056192)
#define OFF_MZ     (OFF_EZ + 8192)
#define OFF_WIHP   (OFF_MZ + 128)              // 1536*1552
#define SCRATCH_FLOATS (OFF_WIHP + 2383872)

__device__ float g_scratch[SCRATCH_FLOATS];

// ---------------- helpers ----------------
__device__ __forceinline__ uint32_t f2tf32(float f) {
    uint32_t r;
    asm("cvt.rna.tf32.f32 %0, %1;" : "=r"(r) : "f"(f));
    return r;
}

__device__ __forceinline__ void mma_tf32(float* c, const uint32_t* a,
                                         uint32_t b0, uint32_t b1) {
    asm volatile(
        "mma.sync.aligned.m16n8k8.row.col.f32.tf32.tf32.f32 "
        "{%0,%1,%2,%3}, {%4,%5,%6,%7}, {%8,%9}, {%0,%1,%2,%3};"
        : "+f"(c[0]), "+f"(c[1]), "+f"(c[2]), "+f"(c[3])
        : "r"(a[0]), "r"(a[1]), "r"(a[2]), "r"(a[3]), "r"(b0), "r"(b1));
}

// ---------------- TF32 NT GEMM ----------------
// C = A(MxK, lda) @ Bw(NxK, ldb, +bofs)^T
// Plain (FUSED=0): splitK via gridDim.z; slice z writes at C + z*M*ldc.
//                  If gridDim.z==1 and bias!=nullptr, bias is added inline.
// Fused (FUSED=1): per (row, n-block) partial of sum_col tanh(acc + bias + pre[b,col]) * wv
//                  with b = row % BATCH; wv = PERB ? wvec[b*N+col] : wvec[col].
#define BM 128
#define BN 128
#define BK 16
#define PAD 20

template<int FUSED, int PERB>
__global__ void __launch_bounds__(256, 2)
gemm_tf32(const float* __restrict__ A, int lda,
          const float* __restrict__ Bw, int ldb, int bofs,
          const float* __restrict__ bias,
          const float* __restrict__ pre,
          const float* __restrict__ wvec,
          float* __restrict__ C, int ldc,
          int M, int N, int K)
{
    __shared__ __align__(16) uint32_t As[2][BM][PAD];
    __shared__ __align__(16) uint32_t Bs[2][BN][PAD];
    __shared__ float red[BM][2];

    const int tid = threadIdx.x;
    const int lane = tid & 31, wid = tid >> 5;
    const int warpRow = wid & 3, warpCol = wid >> 2;
    const int row0 = blockIdx.y * BM, col0 = blockIdx.x * BN;

    const int nkTot = K / BK;
    const int nz = gridDim.z;
    const int kPer = (nkTot + nz - 1) / nz;
    const int kt0 = blockIdx.z * kPer;
    int kt1 = kt0 + kPer; if (kt1 > nkTot) kt1 = nkTot;

    float acc[2][8][4];
    #pragma unroll
    for (int i = 0; i < 2; i++)
        #pragma unroll
        for (int j = 0; j < 8; j++)
            #pragma unroll
            for (int l = 0; l < 4; l++) acc[i][j][l] = 0.f;

    float4 ra[2], rb[2];

    auto gload = [&](int kt) {
        const int kbase = kt * BK;
        #pragma unroll
        for (int h = 0; h < 2; h++) {
            int idx = tid + h * 256;
            int r = idx >> 2, kq = (idx & 3) << 2;
            ra[h] = *(const float4*)(A + (size_t)(row0 + r) * lda + kbase + kq);
            int cn = col0 + r;
            if (cn < N)
                rb[h] = *(const float4*)(Bw + (size_t)cn * ldb + bofs + kbase + kq);
            else
                rb[h] = make_float4(0.f, 0.f, 0.f, 0.f);
        }
    };
    auto sstore = [&](int buf) {
        #pragma unroll
        for (int h = 0; h < 2; h++) {
            int idx = tid + h * 256;
            int r = idx >> 2, kq = (idx & 3) << 2;
            uint4 ua, ub;
            ua.x = f2tf32(ra[h].x); ua.y = f2tf32(ra[h].y);
            ua.z = f2tf32(ra[h].z); ua.w = f2tf32(ra[h].w);
            ub.x = f2tf32(rb[h].x); ub.y = f2tf32(rb[h].y);
            ub.z = f2tf32(rb[h].z); ub.w = f2tf32(rb[h].w);
            *(uint4*)&As[buf][r][kq] = ua;
            *(uint4*)&Bs[buf][r][kq] = ub;
        }
    };

    gload(kt0);
    sstore(0);
    __syncthreads();

    int buf = 0;
    for (int kt = kt0; kt < kt1; kt++) {
        if (kt + 1 < kt1) gload(kt + 1);

        #pragma unroll
        for (int ks = 0; ks < 2; ks++) {
            const int k = ks * 8 + (lane & 3);
            uint32_t a[2][4];
            #pragma unroll
            for (int mi = 0; mi < 2; mi++) {
                int r = warpRow * 32 + mi * 16 + (lane >> 2);
                a[mi][0] = As[buf][r][k];
                a[mi][1] = As[buf][r + 8][k];
                a[mi][2] = As[buf][r][k + 4];
                a[mi][3] = As[buf][r + 8][k + 4];
            }
            #pragma unroll
            for (int ni = 0; ni < 8; ni++) {
                int cb = warpCol * 64 + ni * 8 + (lane >> 2);
                uint32_t b0 = Bs[buf][cb][k];
                uint32_t b1 = Bs[buf][cb][k + 4];
                #pragma unroll
                for (int mi = 0; mi < 2; mi++)
                    mma_tf32(acc[mi][ni], a[mi], b0, b1);
            }
        }

        if (kt + 1 < kt1) sstore(buf ^ 1);
        __syncthreads();
        buf ^= 1;
    }

    if (!FUSED) {
        float* Cb = C + (size_t)blockIdx.z * ((size_t)M * ldc);
        #pragma unroll
        for (int mi = 0; mi < 2; mi++) {
            int r = row0 + warpRow * 32 + mi * 16 + (lane >> 2);
            #pragma unroll
            for (int ni = 0; ni < 8; ni++) {
                int cb = col0 + warpCol * 64 + ni * 8 + 2 * (lane & 3);
                float bs0 = (bias && cb < N)     ? bias[cb]     : 0.f;
                float bs1 = (bias && cb + 1 < N) ? bias[cb + 1] : 0.f;
                if (cb < N)     Cb[(size_t)r * ldc + cb]           = acc[mi][ni][0] + bs0;
                if (cb + 1 < N) Cb[(size_t)r * ldc + cb + 1]       = acc[mi][ni][1] + bs1;
                if (cb < N)     Cb[(size_t)(r + 8) * ldc + cb]     = acc[mi][ni][2] + bs0;
                if (cb + 1 < N) Cb[(size_t)(r + 8) * ldc + cb + 1] = acc[mi][ni][3] + bs1;
            }
        }
    } else {
        #pragma unroll
        for (int mi = 0; mi < 2; mi++) {
            int rl = warpRow * 32 + mi * 16 + (lane >> 2);   // local row
            int bL = rl, bH = rl + 8;                        // b = row % 128
            float s0 = 0.f, s1 = 0.f;
            #pragma unroll
            for (int ni = 0; ni < 8; ni++) {
                int colL = warpCol * 64 + ni * 8 + 2 * (lane & 3);
                #pragma unroll
                for (int j = 0; j < 2; j++) {
                    int gc = col0 + colL + j;
                    float bs = bias ? bias[gc] : 0.f;
                    float e0 = acc[mi][ni][j]     + bs;
                    float e1 = acc[mi][ni][2 + j] + bs;
                    if (pre) { e0 += pre[bL * N + gc]; e1 += pre[bH * N + gc]; }
                    e0 = tanhf(e0); e1 = tanhf(e1);
                    float w0 = PERB ? wvec[bL * N + gc] : wvec[gc];
                    float w1 = PERB ? wvec[bH * N + gc] : wvec[gc];
                    s0 += e0 * w0;
                    s1 += e1 * w1;
                }
            }
            s0 += __shfl_xor_sync(0xffffffffu, s0, 1);
            s0 += __shfl_xor_sync(0xffffffffu, s0, 2);
            s1 += __shfl_xor_sync(0xffffffffu, s1, 1);
            s1 += __shfl_xor_sync(0xffffffffu, s1, 2);
            if ((lane & 3) == 0) {
                red[rl][warpCol]     = s0;
                red[rl + 8][warpCol] = s1;
            }
        }
        __syncthreads();
        if (tid < BM) {
            float s = red[tid][0] + red[tid][1];
            C[(size_t)(row0 + tid) * gridDim.x + blockIdx.x] = s;
        }
    }
}

// sum split-K slices + bias -> dst (row-major with stride ldd)
__global__ void reduceK(const float* __restrict__ part, int slices, int M, int N,
                        const float* __restrict__ bias, float* __restrict__ dst, int ldd)
{
    int i = blockIdx.x * blockDim.x + threadIdx.x;
    if (i >= M * N) return;
    int m = i / N, n = i - m * N;
    float s = bias ? bias[n] : 0.f;
    for (int z = 0; z < slices; z++) s += part[(size_t)z * M * N + i];
    dst[(size_t)m * ldd + n] = s;
}

// sum G n-block partials per row (fused-score reduce)
__global__ void reduceN(const float* __restrict__ part, float* __restrict__ out,
                        int M, int G)
{
    int m = blockIdx.x * blockDim.x + threadIdx.x;
    if (m < M) {
        float s = 0.f;
        for (int g = 0; g < G; g++) s += part[(size_t)m * G + g];
        out[m] = s;
    }
}

// pad-copy Wih (1536 x 1541) -> (1536 x 1552), zero-filled tail
__global__ void padWih(const float* __restrict__ W, float* __restrict__ Wp)
{
    int i = blockIdx.x * blockDim.x + threadIdx.x;
    if (i >= NG * GINP) return;
    int n = i / GINP, k = i - n * GINP;
    Wp[i] = (k < GINR) ? W[(size_t)n * GINR + k] : 0.f;
}

// per-b softmax over T scores (score[t*BATCH + b]) + context weighted sum (float4)
__global__ void softmax_ctx(const float* __restrict__ score,
                            const float* __restrict__ enc,   // (T,B,H)
                            float* __restrict__ ctx, int T)
{
    int b = blockIdx.x, tid = threadIdx.x;        // 128 threads
    __shared__ float sw[128];
    __shared__ float red[128];

    float v = -1e30f;
    if (tid < T) { v = score[tid * BATCH + b]; }
    red[tid] = v;
    __syncthreads();
    for (int s = 64; s > 0; s >>= 1) { if (tid < s) red[tid] = fmaxf(red[tid], red[tid + s]); __syncthreads(); }
    float mx = red[0];
    __syncthreads();

    float e = 0.f;
    if (tid < T) e = expf(v - mx);
    red[tid] = e;
    __syncthreads();
    for (int s = 64; s > 0; s >>= 1) { if (tid < s) red[tid] += red[tid + s]; __syncthreads(); }
    float inv = 1.f / red[0];
    __syncthreads();
    sw[tid] = e * inv;         // zero for tid >= T (e=0)
    __syncthreads();

    // ctx: HDIM/4 = 128 float4 lanes, one per thread
    const float4* enc4 = (const float4*)enc;
    int h4 = tid;              // 0..127
    float4 acc = make_float4(0.f, 0.f, 0.f, 0.f);
    for (int t = 0; t < T; t++) {
        float w = sw[t];
        float4 x = enc4[((size_t)t * BATCH + b) * (HDIM / 4) + h4];
        acc.x += w * x.x; acc.y += w * x.y; acc.z += w * x.z; acc.w += w * x.w;
    }
    ((float4*)ctx)[b * (HDIM / 4) + h4] = acc;
}

// copy-score: per-b max + exp (unnormalized)
__global__ void copy_exp(const float* __restrict__ score,
                         float* __restrict__ ez, float* __restrict__ mz)
{
    int b = blockIdx.x, t = threadIdx.x;          // 64 threads
    __shared__ float sv[64];
    __shared__ float red[64];
    float v = score[t * BATCH + b];
    sv[t] = v; red[t] = v;
    __syncthreads();
    for (int s = 32; s > 0; s >>= 1) { if (t < s) red[t] = fmaxf(red[t], red[t + s]); __syncthreads(); }
    float mx = red[0];
    ez[b * TZ + t] = expf(sv[t] - mx);
    if (t == 0) mz[b] = mx;
}

// z_copy = log(sum_t e[b,t] * sparse[b,t,v]) + m[b] -> S cols [VOC, VOC+PV)  (float4)
__global__ void zcopy_kernel(const float* __restrict__ sp,
                             const float* __restrict__ ez,
                             const float* __restrict__ mz,
                             float* __restrict__ S)
{
    int b = blockIdx.y;
    int v4 = blockIdx.x * blockDim.x + threadIdx.x;
    __shared__ float e[TZ];
    if (threadIdx.x < TZ) e[threadIdx.x] = ez[b * TZ + threadIdx.x];
    __syncthreads();
    if (v4 < PV / 4) {
        const float4* row = (const float4*)(sp + (size_t)b * TZ * PV) + v4;
        float4 acc = make_float4(0.f, 0.f, 0.f, 0.f);
        #pragma unroll 4
        for (int t = 0; t < TZ; t++) {
            float w = e[t];
            float4 x = row[(size_t)t * (PV / 4)];
            acc.x += w * x.x; acc.y += w * x.y; acc.z += w * x.z; acc.w += w * x.w;
        }
        float m = mz[b];
        float* dst = S + (size_t)b * SLD + VOC + 4 * v4;
        dst[0] = logf(acc.x) + m;
        dst[1] = logf(acc.y) + m;
        dst[2] = logf(acc.z) + m;
        dst[3] = logf(acc.w) + m;
    }
}

// gin = [m_embed(512) | u_ctx(512) | z_ctx(512) | degree(5) | zero pad]
__global__ void build_gin(const int* __restrict__ mt, const float* __restrict__ emb,
                          const float* __restrict__ ctxU, const float* __restrict__ ctxZ,
                          const float* __restrict__ degree, float* __restrict__ gin)
{
    int b = blockIdx.x;
    int m = mt[b];
    for (int i = threadIdx.x; i < GINP; i += blockDim.x) {
        float v;
        if (i < 512)       v = emb[(size_t)m * 512 + i];
        else if (i < 1024) v = ctxU[b * HDIM + (i - 512)];
        else if (i < 1536) v = ctxZ[b * HDIM + (i - 1024)];
        else if (i < GINR) v = degree[b * DDIM + (i - 1536)];
        else               v = 0.f;
        gin[(size_t)b * GINP + i] = v;
    }
}

// GRU gates -> h_new; assemble gencat; also write gru_out (x2) into out tail
__global__ void gru_gate(const float* __restrict__ gi, const float* __restrict__ gh,
                         const float* __restrict__ hprev,
                         const float* __restrict__ ctxZ, const float* __restrict__ ctxU,
                         float* __restrict__ hnew, float* __restrict__ gencat,
                         float* __restrict__ out, int out_size)
{
    int idx = blockIdx.x * blockDim.x + threadIdx.x;
    if (idx >= BATCH * HDIM) return;
    int b = idx >> 9, j = idx & 511;
    const float* gib = gi + (size_t)b * NG;
    const float* ghb = gh + (size_t)b * NG;
    float r = 1.f / (1.f + expf(-(gib[j]        + ghb[j])));
    float z = 1.f / (1.f + expf(-(gib[512 + j]  + ghb[512 + j])));
    float n = tanhf(gib[1024 + j] + r * ghb[1024 + j]);
    float h = (1.f - z) * n + z * hprev[idx];
    hnew[idx] = h;
    gencat[(size_t)b * NG + j]        = ctxZ[idx];
    gencat[(size_t)b * NG + 512 + j]  = ctxU[idx];
    gencat[(size_t)b * NG + 1024 + j] = h;
    const int base = BATCH * PV;
    if (out_size >= base + BATCH * HDIM)     out[base + idx] = h;
    if (out_size >= base + 2 * BATCH * HDIM) out[base + BATCH * HDIM + idx] = h;
}

// final softmax over SLD -> proba = [gen + cp[:, :V] | cp[:, V:]]  (float4)
__global__ void final_softmax(const float* __restrict__ S, float* __restrict__ out)
{
    int b = blockIdx.x, tid = threadIdx.x;        // 256 threads
    __shared__ float red[256];
    const float4* row4 = (const float4*)(S + (size_t)b * SLD);
    const int n4 = SLD / 4;                       // 4016

    float mx = -1e30f;
    for (int i = tid; i < n4; i += 256) {
        float4 x = row4[i];
        mx = fmaxf(mx, fmaxf(fmaxf(x.x, x.y), fmaxf(x.z, x.w)));
    }
    red[tid] = mx;
    __syncthreads();
    for (int s = 128; s > 0; s >>= 1) { if (tid < s) red[tid] = fmaxf(red[tid], red[tid + s]); __syncthreads(); }
    mx = red[0];
    __syncthreads();

    float sm = 0.f;
    for (int i = tid; i < n4; i += 256) {
        float4 x = row4[i];
        sm += expf(x.x - mx) + expf(x.y - mx) + expf(x.z - mx) + expf(x.w - mx);
    }
    red[tid] = sm;
    __syncthreads();
    for (int s = 128; s > 0; s >>= 1) { if (tid < s) red[tid] += red[tid + s]; __syncthreads(); }
    float inv = 1.f / red[0];

    const float4* cp4 = (const float4*)(S + (size_t)b * SLD + VOC);
    float4* out4 = (float4*)(out + (size_t)b * PV);
    for (int i = tid; i < PV / 4; i += 256) {
        float4 c = cp4[i];
        float4 o;
        o.x = expf(c.x - mx) * inv;
        o.y = expf(c.y - mx) * inv;
        o.z = expf(c.z - mx) * inv;
        o.w = expf(c.w - mx) * inv;
        if (i < VOC / 4) {
            float4 g = row4[i];
            o.x += expf(g.x - mx) * inv;
            o.y += expf(g.y - mx) * inv;
            o.z += expf(g.z - mx) * inv;
            o.w += expf(g.w - mx) * inv;
        }
        out4[i] = o;
    }
}

// ---------------------------------------------------------------------------
static cudaStream_t g_s1, g_s2, g_s3;
static cudaEvent_t g_evRoot, g_evU, g_evP, g_evH, g_evG, g_evS;
static bool g_init = false;

extern "C" void kernel_launch(void* const* d_in, const int* in_sizes, int n_in,
                              void* d_out, int out_size)
{
    // One-time creation of streams/events. Happens on the (uncaptured)
    // correctness call; no device memory is allocated. Work per call is
    // identical regardless.
    if (!g_init) {
        cudaStreamCreateWithFlags(&g_s1, cudaStreamNonBlocking);
        cudaStreamCreateWithFlags(&g_s2, cudaStreamNonBlocking);
        cudaStreamCreateWithFlags(&g_s3, cudaStreamNonBlocking);
        cudaEventCreateWithFlags(&g_evRoot, cudaEventDisableTiming);
        cudaEventCreateWithFlags(&g_evU,    cudaEventDisableTiming);
        cudaEventCreateWithFlags(&g_evP,    cudaEventDisableTiming);
        cudaEventCreateWithFlags(&g_evH,    cudaEventDisableTiming);
        cudaEventCreateWithFlags(&g_evG,    cudaEventDisableTiming);
        cudaEventCreateWithFlags(&g_evS,    cudaEventDisableTiming);
        g_init = true;
    }

    const float* z_enc  = (const float*)d_in[0];   // (64,128,512)
    const float* u_enc  = (const float*)d_in[1];   // (128,128,512)
    const int*   mt     = (const int*)d_in[2];     // (1,128)
    const float* degree = (const float*)d_in[3];   // (128,5)
    const float* hid    = (const float*)d_in[4];   // (1,128,512)
    const float* sp     = (const float*)d_in[5];   // (128,64,8064)
    const float* emb    = (const float*)d_in[6];   // (8000,512)
    const float* azW    = (const float*)d_in[7];   // (512,1024)
    const float* azb    = (const float*)d_in[8];
    const float* azv    = (const float*)d_in[9];
    const float* auW    = (const float*)d_in[10];
    const float* aub    = (const float*)d_in[11];
    const float* auv    = (const float*)d_in[12];
    const float* Wih    = (const float*)d_in[13];  // (1536,1541)
    const float* Whh    = (const float*)d_in[14];  // (1536,512)
    const float* bih    = (const float*)d_in[15];
    const float* bhh    = (const float*)d_in[16];
    const float* pW     = (const float*)d_in[17];  // (8000,1536)
    const float* pb     = (const float*)d_in[18];
    const float* c2W    = (const float*)d_in[19];  // (512,512)
    const float* c2b    = (const float*)d_in[20];
    float* out = (float*)d_out;

    float* base = nullptr;
    cudaGetSymbolAddress((void**)&base, g_scratch);
    float* preZ   = base + OFF_PREZ;
    float* preU   = base + OFF_PREU;
    float* partZ  = base + OFF_PARTZ;
    float* partU  = base + OFF_PARTU;
    float* partC  = base + OFF_PARTC;
    float* partGI = base + OFF_PARTGI;
    float* partPJ = base + OFF_PARTPJ;
    float* scoreZ = base + OFF_SCZ;
    float* scoreU = base + OFF_SCU;
    float* scoreC = base + OFF_SCC;
    float* ctxZ   = base + OFF_CTXZ;
    float* ctxU   = base + OFF_CTXU;
    float* gin    = base + OFF_GIN;
    float* gi     = base + OFF_GI;
    float* gh     = base + OFF_GH;
    float* hnew   = base + OFF_HNEW;
    float* gencat = base + OFF_GENCAT;
    float* S      = base + OFF_S;
    float* ez     = base + OFF_EZ;
    float* mz     = base + OFF_MZ;
    float* Wihp   = base + OFF_WIHP;

    // ---- fork: root event on capture (default) stream ----
    cudaEventRecord(g_evRoot, 0);
    cudaStreamWaitEvent(g_s1, g_evRoot, 0);
    cudaStreamWaitEvent(g_s2, g_evRoot, 0);
    cudaStreamWaitEvent(g_s3, g_evRoot, 0);

    // ---- s3: pad Wih (needed only by gi GEMM) ----
    padWih<<<(NG * GINP + 255) / 256, 256, 0, g_s3>>>(Wih, Wihp);

    // ---- s2: gh = hid @ Whh^T + bhh (bias inline, no splitK) ----
    gemm_tf32<0,0><<<dim3(12, 1, 1), 256, 0, g_s2>>>(hid, HDIM, Whh, HDIM, 0,
                                                     bhh, nullptr, nullptr,
                                                     gh, NG, BATCH, NG, HDIM);

    // ---- default stream: Z attention chain ----
    gemm_tf32<0,0><<<dim3(4, 1, 1), 256>>>(hid, HDIM, azW, 2*HDIM, 0,
                                           azb, nullptr, nullptr,
                                           preZ, HDIM, BATCH, HDIM, HDIM);
    gemm_tf32<1,0><<<dim3(4, 64, 1), 256>>>(z_enc, HDIM, azW, 2*HDIM, HDIM,
                                            nullptr, preZ, azv,
                                            partZ, 0, TZ*BATCH, HDIM, HDIM);
    reduceN<<<(TZ * BATCH) / 256, 256>>>(partZ, scoreZ, TZ * BATCH, 4);
    softmax_ctx<<<BATCH, 128>>>(scoreZ, z_enc, ctxZ, TZ);

    // ---- s1: U attention chain ----
    gemm_tf32<0,0><<<dim3(4, 1, 1), 256, 0, g_s1>>>(hid, HDIM, auW, 2*HDIM, 0,
                                                    aub, nullptr, nullptr,
                                                    preU, HDIM, BATCH, HDIM, HDIM);
    gemm_tf32<1,0><<<dim3(4, 128, 1), 256, 0, g_s1>>>(u_enc, HDIM, auW, 2*HDIM, HDIM,
                                                      nullptr, preU, auv,
                                                      partU, 0, TU*BATCH, HDIM, HDIM);
    reduceN<<<(TU * BATCH) / 256, 256, 0, g_s1>>>(partU, scoreU, TU * BATCH, 4);
    softmax_ctx<<<BATCH, 128, 0, g_s1>>>(scoreU, u_enc, ctxU, TU);

    // ---- join U into default; build gin; join padWih; gi GEMM ----
    cudaEventRecord(g_evU, g_s1);
    cudaStreamWaitEvent(0, g_evU, 0);
    build_gin<<<BATCH, 256>>>(mt, emb, ctxU, ctxZ, degree, gin);
    cudaEventRecord(g_evP, g_s3);
    cudaStreamWaitEvent(0, g_evP, 0);
    gemm_tf32<0,0><<<dim3(12, 1, 4), 256>>>(gin, GINP, Wihp, GINP, 0,
                                            nullptr, nullptr, nullptr,
                                            partGI, NG, BATCH, NG, GINP);
    reduceK<<<(BATCH * NG + 255) / 256, 256>>>(partGI, 4, BATCH, NG, bih, gi, NG);

    // ---- join gh; GRU gates (+ gru_out write) ----
    cudaEventRecord(g_evH, g_s2);
    cudaStreamWaitEvent(0, g_evH, 0);
    gru_gate<<<(BATCH * HDIM) / 256, 256>>>(gi, gh, hid, ctxZ, ctxU, hnew, gencat,
                                            out, out_size);

    // ---- fork: proj chain on s1, copy chain on default ----
    cudaEventRecord(g_evG, 0);
    cudaStreamWaitEvent(g_s1, g_evG, 0);

    // s1: projection -> S[:, :V] (splitK=4)
    gemm_tf32<0,0><<<dim3(63, 1, 4), 256, 0, g_s1>>>(gencat, NG, pW, NG, 0,
                                                     nullptr, nullptr, nullptr,
                                                     partPJ, VOC, BATCH, VOC, NG);
    reduceK<<<(BATCH * VOC + 255) / 256, 256, 0, g_s1>>>(partPJ, 4, BATCH, VOC, pb, S, SLD);

    // default: copy-score GEMM -> z_copy -> S[:, V:]
    gemm_tf32<1,1><<<dim3(4, 64, 1), 256>>>(z_enc, HDIM, c2W, HDIM, 0,
                                            c2b, nullptr, hnew,
                                            partC, 0, TZ*BATCH, HDIM, HDIM);
    reduceN<<<(TZ * BATCH) / 256, 256>>>(partC, scoreC, TZ * BATCH, 4);
    copy_exp<<<BATCH, TZ>>>(scoreC, ez, mz);
    zcopy_kernel<<<dim3((PV / 4 + 255) / 256, BATCH), 256>>>(sp, ez, mz, S);

    // ---- join proj; final softmax ----
    cudaEventRecord(g_evS, g_s1);
    cudaStreamWaitEvent(0, g_evS, 0);
    final_softmax<<<BATCH, 256>>>(S, out);
}

// round 7
// speedup vs baseline: 3.8832x; 1.1983x over previous
#include <cuda_runtime.h>
#include <math.h>
#include <stdint.h>

// ---------------- problem constants ----------------
#define BATCH 128
#define HDIM  512
#define TZ    64
#define TU    128
#define DDIM  5
#define VOC   8000
#define GINR  1541          // real gin width
#define GINP  1552          // padded to multiple of 16
#define NG    1536          // 3H
#define PV    8064          // V + TZ
#define SLD   16064         // V + PV

// ---------------- scratch offsets (floats) ----------------
#define OFF_PREZ   0
#define OFF_PREU   (OFF_PREZ + 65536)
#define OFF_PARTZ  (OFF_PREU + 65536)          // 8192*4
#define OFF_PARTU  (OFF_PARTZ + 32768)         // 16384*4
#define OFF_PARTGI (OFF_PARTU + 65536)         // 8*128*1536
#define OFF_PARTPJ (OFF_PARTGI + 1572864)      // 4*128*8000
#define OFF_SCZ    (OFF_PARTPJ + 4096000)
#define OFF_SCU    (OFF_SCZ + 8192)
#define OFF_SCC    (OFF_SCU + 16384)
#define OFF_CTXZ   (OFF_SCC + 8192)
#define OFF_CTXU   (OFF_CTXZ + 65536)
#define OFF_GIN    (OFF_CTXU + 65536)          // 128*1552
#define OFF_GI     (OFF_GIN + 198656)
#define OFF_GH     (OFF_GI + 196608)
#define OFF_HNEW   (OFF_GH + 196608)
#define OFF_GENCAT (OFF_HNEW + 65536)
#define OFF_S      (OFF_GENCAT + 196608)       // 128*16064
#define OFF_EZ     (OFF_S + 2056192)
#define OFF_MZ     (OFF_EZ + 8192)
#define OFF_WIHP   (OFF_MZ + 128)              // 1536*1552
#define OFF_CS     (OFF_WIHP + 2383872)        // 8192*512
#define SCRATCH_FLOATS (OFF_CS + 4194304)

__device__ float g_scratch[SCRATCH_FLOATS];

// ---------------- helpers ----------------
__device__ __forceinline__ float ftanh(float x) {
    // 1 - 2/(e^{2x}+1); exact at +-inf, rel err ~1e-6 (MUFU-based)
    float e = __expf(2.f * x);
    return 1.f - __fdividef(2.f, e + 1.f);
}

__device__ __forceinline__ uint32_t f2tf32(float f) {
    uint32_t r;
    asm("cvt.rna.tf32.f32 %0, %1;" : "=r"(r) : "f"(f));
    return r;
}

__device__ __forceinline__ void mma_tf32(float* c, const uint32_t* a,
                                         uint32_t b0, uint32_t b1) {
    asm volatile(
        "mma.sync.aligned.m16n8k8.row.col.f32.tf32.tf32.f32 "
        "{%0,%1,%2,%3}, {%4,%5,%6,%7}, {%8,%9}, {%0,%1,%2,%3};"
        : "+f"(c[0]), "+f"(c[1]), "+f"(c[2]), "+f"(c[3])
        : "r"(a[0]), "r"(a[1]), "r"(a[2]), "r"(a[3]), "r"(b0), "r"(b1));
}

// ---------------- TF32 NT GEMM ----------------
// C = A(MxK, lda) @ Bw(NxK, ldb, +bofs)^T
// EPI=0: plain; splitK via gridDim.z (slice z at C + z*M*ldc, no bias);
//        if gridDim.z==1 and bias, bias added inline.
// EPI=1: fused score partials: sum_col ftanh(acc + bias + pre[b,col]) * wv,
//        b = row % BATCH; wv = PERB ? wvec[b*N+col] : wvec[col].
// EPI=2: write ftanh(acc + bias) elementwise (nz must be 1).
#define BM 128
#define BN 128
#define BK 16
#define PAD 20

template<int EPI, int PERB>
__global__ void __launch_bounds__(256, 2)
gemm_tf32(const float* __restrict__ A, int lda,
          const float* __restrict__ Bw, int ldb, int bofs,
          const float* __restrict__ bias,
          const float* __restrict__ pre,
          const float* __restrict__ wvec,
          float* __restrict__ C, int ldc,
          int M, int N, int K)
{
    __shared__ __align__(16) uint32_t As[2][BM][PAD];
    __shared__ __align__(16) uint32_t Bs[2][BN][PAD];
    __shared__ float red[BM][2];

    const int tid = threadIdx.x;
    const int lane = tid & 31, wid = tid >> 5;
    const int warpRow = wid & 3, warpCol = wid >> 2;
    const int row0 = blockIdx.y * BM, col0 = blockIdx.x * BN;

    const int nkTot = K / BK;
    const int nz = gridDim.z;
    const int kPer = (nkTot + nz - 1) / nz;
    const int kt0 = blockIdx.z * kPer;
    int kt1 = kt0 + kPer; if (kt1 > nkTot) kt1 = nkTot;

    float acc[2][8][4];
    #pragma unroll
    for (int i = 0; i < 2; i++)
        #pragma unroll
        for (int j = 0; j < 8; j++)
            #pragma unroll
            for (int l = 0; l < 4; l++) acc[i][j][l] = 0.f;

    float4 ra[2], rb[2];

    auto gload = [&](int kt) {
        const int kbase = kt * BK;
        #pragma unroll
        for (int h = 0; h < 2; h++) {
            int idx = tid + h * 256;
            int r = idx >> 2, kq = (idx & 3) << 2;
            ra[h] = *(const float4*)(A + (size_t)(row0 + r) * lda + kbase + kq);
            int cn = col0 + r;
            if (cn < N)
                rb[h] = *(const float4*)(Bw + (size_t)cn * ldb + bofs + kbase + kq);
            else
                rb[h] = make_float4(0.f, 0.f, 0.f, 0.f);
        }
    };
    auto sstore = [&](int buf) {
        #pragma unroll
        for (int h = 0; h < 2; h++) {
            int idx = tid + h * 256;
            int r = idx >> 2, kq = (idx & 3) << 2;
            uint4 ua, ub;
            ua.x = f2tf32(ra[h].x); ua.y = f2tf32(ra[h].y);
            ua.z = f2tf32(ra[h].z); ua.w = f2tf32(ra[h].w);
            ub.x = f2tf32(rb[h].x); ub.y = f2tf32(rb[h].y);
            ub.z = f2tf32(rb[h].z); ub.w = f2tf32(rb[h].w);
            *(uint4*)&As[buf][r][kq] = ua;
            *(uint4*)&Bs[buf][r][kq] = ub;
        }
    };

    gload(kt0);
    sstore(0);
    __syncthreads();

    int buf = 0;
    for (int kt = kt0; kt < kt1; kt++) {
        if (kt + 1 < kt1) gload(kt + 1);

        #pragma unroll
        for (int ks = 0; ks < 2; ks++) {
            const int k = ks * 8 + (lane & 3);
            uint32_t a[2][4];
            #pragma unroll
            for (int mi = 0; mi < 2; mi++) {
                int r = warpRow * 32 + mi * 16 + (lane >> 2);
                a[mi][0] = As[buf][r][k];
                a[mi][1] = As[buf][r + 8][k];
                a[mi][2] = As[buf][r][k + 4];
                a[mi][3] = As[buf][r + 8][k + 4];
            }
            #pragma unroll
            for (int ni = 0; ni < 8; ni++) {
                int cb = warpCol * 64 + ni * 8 + (lane >> 2);
                uint32_t b0 = Bs[buf][cb][k];
                uint32_t b1 = Bs[buf][cb][k + 4];
                #pragma unroll
                for (int mi = 0; mi < 2; mi++)
                    mma_tf32(acc[mi][ni], a[mi], b0, b1);
            }
        }

        if (kt + 1 < kt1) sstore(buf ^ 1);
        __syncthreads();
        buf ^= 1;
    }

    if (EPI != 1) {
        float* Cb = C + (size_t)blockIdx.z * ((size_t)M * ldc);
        #pragma unroll
        for (int mi = 0; mi < 2; mi++) {
            int r = row0 + warpRow * 32 + mi * 16 + (lane >> 2);
            #pragma unroll
            for (int ni = 0; ni < 8; ni++) {
                int cb = col0 + warpCol * 64 + ni * 8 + 2 * (lane & 3);
                float bs0 = (bias && cb < N)     ? bias[cb]     : 0.f;
                float bs1 = (bias && cb + 1 < N) ? bias[cb + 1] : 0.f;
                float v00 = acc[mi][ni][0] + bs0;
                float v01 = acc[mi][ni][1] + bs1;
                float v10 = acc[mi][ni][2] + bs0;
                float v11 = acc[mi][ni][3] + bs1;
                if (EPI == 2) {
                    v00 = ftanh(v00); v01 = ftanh(v01);
                    v10 = ftanh(v10); v11 = ftanh(v11);
                }
                if (cb < N)     Cb[(size_t)r * ldc + cb]           = v00;
                if (cb + 1 < N) Cb[(size_t)r * ldc + cb + 1]       = v01;
                if (cb < N)     Cb[(size_t)(r + 8) * ldc + cb]     = v10;
                if (cb + 1 < N) Cb[(size_t)(r + 8) * ldc + cb + 1] = v11;
            }
        }
    } else {
        #pragma unroll
        for (int mi = 0; mi < 2; mi++) {
            int rl = warpRow * 32 + mi * 16 + (lane >> 2);   // local row
            int bL = rl, bH = rl + 8;                        // b = row % 128
            float s0 = 0.f, s1 = 0.f;
            #pragma unroll
            for (int ni = 0; ni < 8; ni++) {
                int colL = warpCol * 64 + ni * 8 + 2 * (lane & 3);
                #pragma unroll
                for (int j = 0; j < 2; j++) {
                    int gc = col0 + colL + j;
                    float bs = bias ? bias[gc] : 0.f;
                    float e0 = acc[mi][ni][j]     + bs;
                    float e1 = acc[mi][ni][2 + j] + bs;
                    if (pre) { e0 += pre[bL * N + gc]; e1 += pre[bH * N + gc]; }
                    e0 = ftanh(e0); e1 = ftanh(e1);
                    float w0 = PERB ? wvec[bL * N + gc] : wvec[gc];
                    float w1 = PERB ? wvec[bH * N + gc] : wvec[gc];
                    s0 += e0 * w0;
                    s1 += e1 * w1;
                }
            }
            s0 += __shfl_xor_sync(0xffffffffu, s0, 1);
            s0 += __shfl_xor_sync(0xffffffffu, s0, 2);
            s1 += __shfl_xor_sync(0xffffffffu, s1, 1);
            s1 += __shfl_xor_sync(0xffffffffu, s1, 2);
            if ((lane & 3) == 0) {
                red[rl][warpCol]     = s0;
                red[rl + 8][warpCol] = s1;
            }
        }
        __syncthreads();
        if (tid < BM) {
            float s = red[tid][0] + red[tid][1];
            C[(size_t)(row0 + tid) * gridDim.x + blockIdx.x] = s;
        }
    }
}

// sum split-K slices + bias -> dst (row-major with stride ldd)
__global__ void reduceK(const float* __restrict__ part, int slices, int M, int N,
                        const float* __restrict__ bias, float* __restrict__ dst, int ldd)
{
    int i = blockIdx.x * blockDim.x + threadIdx.x;
    if (i >= M * N) return;
    int m = i / N, n = i - m * N;
    float s = bias ? bias[n] : 0.f;
    for (int z = 0; z < slices; z++) s += part[(size_t)z * M * N + i];
    dst[(size_t)m * ldd + n] = s;
}

// sum G n-block partials per row (fused-score reduce)
__global__ void reduceN(const float* __restrict__ part, float* __restrict__ out,
                        int M, int G)
{
    int m = blockIdx.x * blockDim.x + threadIdx.x;
    if (m < M) {
        float s = 0.f;
        for (int g = 0; g < G; g++) s += part[(size_t)m * G + g];
        out[m] = s;
    }
}

// pad-copy Wih (1536 x 1541) -> (1536 x 1552), zero-filled tail
__global__ void padWih(const float* __restrict__ W, float* __restrict__ Wp)
{
    int i = blockIdx.x * blockDim.x + threadIdx.x;
    if (i >= NG * GINP) return;
    int n = i / GINP, k = i - n * GINP;
    Wp[i] = (k < GINR) ? W[(size_t)n * GINR + k] : 0.f;
}

// per-b softmax over T scores (score[t*BATCH + b]) + context weighted sum (float4)
__global__ void softmax_ctx(const float* __restrict__ score,
                            const float* __restrict__ enc,   // (T,B,H)
                            float* __restrict__ ctx, int T)
{
    int b = blockIdx.x, tid = threadIdx.x;        // 128 threads
    __shared__ float sw[128];
    __shared__ float red[128];

    float v = -1e30f;
    if (tid < T) { v = score[tid * BATCH + b]; }
    red[tid] = v;
    __syncthreads();
    for (int s = 64; s > 0; s >>= 1) { if (tid < s) red[tid] = fmaxf(red[tid], red[tid + s]); __syncthreads(); }
    float mx = red[0];
    __syncthreads();

    float e = 0.f;
    if (tid < T) e = __expf(v - mx);
    red[tid] = e;
    __syncthreads();
    for (int s = 64; s > 0; s >>= 1) { if (tid < s) red[tid] += red[tid + s]; __syncthreads(); }
    float inv = __fdividef(1.f, red[0]);
    __syncthreads();
    sw[tid] = e * inv;         // zero for tid >= T (e=0)
    __syncthreads();

    const float4* enc4 = (const float4*)enc;
    int h4 = tid;              // 0..127
    float4 acc = make_float4(0.f, 0.f, 0.f, 0.f);
    for (int t = 0; t < T; t++) {
        float w = sw[t];
        float4 x = enc4[((size_t)t * BATCH + b) * (HDIM / 4) + h4];
        acc.x += w * x.x; acc.y += w * x.y; acc.z += w * x.z; acc.w += w * x.w;
    }
    ((float4*)ctx)[b * (HDIM / 4) + h4] = acc;
}

// z_score matvec: scoreC[r] = dot(cs[r,:], hnew[r%128,:]);  r = t*BATCH + b
__global__ void zscore_matvec(const float* __restrict__ cs,
                              const float* __restrict__ hnew,
                              float* __restrict__ scoreC)
{
    int w = threadIdx.x >> 5, lane = threadIdx.x & 31;
    int r = blockIdx.x * 8 + w;                   // 1024 blocks * 8 warps = 8192
    int b = r & (BATCH - 1);
    const float4* crow = (const float4*)(cs + (size_t)r * HDIM);
    const float4* hrow = (const float4*)(hnew + (size_t)b * HDIM);
    float acc = 0.f;
    #pragma unroll
    for (int q = 0; q < 4; q++) {
        float4 c = crow[lane + 32 * q];
        float4 h = hrow[lane + 32 * q];
        acc += c.x * h.x + c.y * h.y + c.z * h.z + c.w * h.w;
    }
    #pragma unroll
    for (int s = 16; s > 0; s >>= 1) acc += __shfl_xor_sync(0xffffffffu, acc, s);
    if (lane == 0) scoreC[r] = acc;
}

// copy-score: per-b max + exp (unnormalized)
__global__ void copy_exp(const float* __restrict__ score,
                         float* __restrict__ ez, float* __restrict__ mz)
{
    int b = blockIdx.x, t = threadIdx.x;          // 64 threads
    __shared__ float sv[64];
    __shared__ float red[64];
    float v = score[t * BATCH + b];
    sv[t] = v; red[t] = v;
    __syncthreads();
    for (int s = 32; s > 0; s >>= 1) { if (t < s) red[t] = fmaxf(red[t], red[t + s]); __syncthreads(); }
    float mx = red[0];
    ez[b * TZ + t] = __expf(sv[t] - mx);
    if (t == 0) mz[b] = mx;
}

// z_copy = log(sum_t e[b,t] * sparse[b,t,v]) + m[b] -> S cols [VOC, VOC+PV)  (float4)
__global__ void zcopy_kernel(const float* __restrict__ sp,
                             const float* __restrict__ ez,
                             const float* __restrict__ mz,
                             float* __restrict__ S)
{
    int b = blockIdx.y;
    int v4 = blockIdx.x * blockDim.x + threadIdx.x;
    __shared__ float e[TZ];
    if (threadIdx.x < TZ) e[threadIdx.x] = ez[b * TZ + threadIdx.x];
    __syncthreads();
    if (v4 < PV / 4) {
        const float4* row = (const float4*)(sp + (size_t)b * TZ * PV) + v4;
        float4 acc = make_float4(0.f, 0.f, 0.f, 0.f);
        #pragma unroll 8
        for (int t = 0; t < TZ; t++) {
            float w = e[t];
            float4 x = row[(size_t)t * (PV / 4)];
            acc.x += w * x.x; acc.y += w * x.y; acc.z += w * x.z; acc.w += w * x.w;
        }
        float m = mz[b];
        float* dst = S + (size_t)b * SLD + VOC + 4 * v4;
        dst[0] = __logf(acc.x) + m;
        dst[1] = __logf(acc.y) + m;
        dst[2] = __logf(acc.z) + m;
        dst[3] = __logf(acc.w) + m;
    }
}

// gin = [m_embed(512) | u_ctx(512) | z_ctx(512) | degree(5) | zero pad]
__global__ void build_gin(const int* __restrict__ mt, const float* __restrict__ emb,
                          const float* __restrict__ ctxU, const float* __restrict__ ctxZ,
                          const float* __restrict__ degree, float* __restrict__ gin)
{
    int b = blockIdx.x;
    int m = mt[b];
    for (int i = threadIdx.x; i < GINP; i += blockDim.x) {
        float v;
        if (i < 512)       v = emb[(size_t)m * 512 + i];
        else if (i < 1024) v = ctxU[b * HDIM + (i - 512)];
        else if (i < 1536) v = ctxZ[b * HDIM + (i - 1024)];
        else if (i < GINR) v = degree[b * DDIM + (i - 1536)];
        else               v = 0.f;
        gin[(size_t)b * GINP + i] = v;
    }
}

// GRU gates -> h_new; assemble gencat; also write gru_out (x2) into out tail
__global__ void gru_gate(const float* __restrict__ gi, const float* __restrict__ gh,
                         const float* __restrict__ hprev,
                         const float* __restrict__ ctxZ, const float* __restrict__ ctxU,
                         float* __restrict__ hnew, float* __restrict__ gencat,
                         float* __restrict__ out, int out_size)
{
    int idx = blockIdx.x * blockDim.x + threadIdx.x;
    if (idx >= BATCH * HDIM) return;
    int b = idx >> 9, j = idx & 511;
    const float* gib = gi + (size_t)b * NG;
    const float* ghb = gh + (size_t)b * NG;
    float r = __fdividef(1.f, 1.f + __expf(-(gib[j]       + ghb[j])));
    float z = __fdividef(1.f, 1.f + __expf(-(gib[512 + j] + ghb[512 + j])));
    float n = ftanh(gib[1024 + j] + r * ghb[1024 + j]);
    float h = (1.f - z) * n + z * hprev[idx];
    hnew[idx] = h;
    gencat[(size_t)b * NG + j]        = ctxZ[idx];
    gencat[(size_t)b * NG + 512 + j]  = ctxU[idx];
    gencat[(size_t)b * NG + 1024 + j] = h;
    const int base = BATCH * PV;
    if (out_size >= base + BATCH * HDIM)     out[base + idx] = h;
    if (out_size >= base + 2 * BATCH * HDIM) out[base + BATCH * HDIM + idx] = h;
}

// final softmax over SLD -> proba = [gen + cp[:, :V] | cp[:, V:]]  (float4)
__global__ void final_softmax(const float* __restrict__ S, float* __restrict__ out)
{
    int b = blockIdx.x, tid = threadIdx.x;        // 256 threads
    __shared__ float red[256];
    const float4* row4 = (const float4*)(S + (size_t)b * SLD);
    const int n4 = SLD / 4;                       // 4016

    float mx = -1e30f;
    for (int i = tid; i < n4; i += 256) {
        float4 x = row4[i];
        mx = fmaxf(mx, fmaxf(fmaxf(x.x, x.y), fmaxf(x.z, x.w)));
    }
    red[tid] = mx;
    __syncthreads();
    for (int s = 128; s > 0; s >>= 1) { if (tid < s) red[tid] = fmaxf(red[tid], red[tid + s]); __syncthreads(); }
    mx = red[0];
    __syncthreads();

    float sm = 0.f;
    for (int i = tid; i < n4; i += 256) {
        float4 x = row4[i];
        sm += __expf(x.x - mx) + __expf(x.y - mx) + __expf(x.z - mx) + __expf(x.w - mx);
    }
    red[tid] = sm;
    __syncthreads();
    for (int s = 128; s > 0; s >>= 1) { if (tid < s) red[tid] += red[tid + s]; __syncthreads(); }
    float inv = __fdividef(1.f, red[0]);

    const float4* cp4 = (const float4*)(S + (size_t)b * SLD + VOC);
    float4* out4 = (float4*)(out + (size_t)b * PV);
    for (int i = tid; i < PV / 4; i += 256) {
        float4 c = cp4[i];
        float4 o;
        o.x = __expf(c.x - mx) * inv;
        o.y = __expf(c.y - mx) * inv;
        o.z = __expf(c.z - mx) * inv;
        o.w = __expf(c.w - mx) * inv;
        if (i < VOC / 4) {
            float4 g = row4[i];
            o.x += __expf(g.x - mx) * inv;
            o.y += __expf(g.y - mx) * inv;
            o.z += __expf(g.z - mx) * inv;
            o.w += __expf(g.w - mx) * inv;
        }
        out4[i] = o;
    }
}

// ---------------------------------------------------------------------------
static cudaStream_t g_s1, g_s2, g_s3;
static cudaEvent_t g_evRoot, g_evU, g_evP, g_evCS, g_evG, g_evS;
static bool g_init = false;

extern "C" void kernel_launch(void* const* d_in, const int* in_sizes, int n_in,
                              void* d_out, int out_size)
{
    if (!g_init) {
        cudaStreamCreateWithFlags(&g_s1, cudaStreamNonBlocking);
        cudaStreamCreateWithFlags(&g_s2, cudaStreamNonBlocking);
        cudaStreamCreateWithFlags(&g_s3, cudaStreamNonBlocking);
        cudaEventCreateWithFlags(&g_evRoot, cudaEventDisableTiming);
        cudaEventCreateWithFlags(&g_evU,    cudaEventDisableTiming);
        cudaEventCreateWithFlags(&g_evP,    cudaEventDisableTiming);
        cudaEventCreateWithFlags(&g_evCS,   cudaEventDisableTiming);
        cudaEventCreateWithFlags(&g_evG,    cudaEventDisableTiming);
        cudaEventCreateWithFlags(&g_evS,    cudaEventDisableTiming);
        g_init = true;
    }

    const float* z_enc  = (const float*)d_in[0];   // (64,128,512)
    const float* u_enc  = (const float*)d_in[1];   // (128,128,512)
    const int*   mt     = (const int*)d_in[2];     // (1,128)
    const float* degree = (const float*)d_in[3];   // (128,5)
    const float* hid    = (const float*)d_in[4];   // (1,128,512)
    const float* sp     = (const float*)d_in[5];   // (128,64,8064)
    const float* emb    = (const float*)d_in[6];   // (8000,512)
    const float* azW    = (const float*)d_in[7];   // (512,1024)
    const float* azb    = (const float*)d_in[8];
    const float* azv    = (const float*)d_in[9];
    const float* auW    = (const float*)d_in[10];
    const float* aub    = (const float*)d_in[11];
    const float* auv    = (const float*)d_in[12];
    const float* Wih    = (const float*)d_in[13];  // (1536,1541)
    const float* Whh    = (const float*)d_in[14];  // (1536,512)
    const float* bih    = (const float*)d_in[15];
    const float* bhh    = (const float*)d_in[16];
    const float* pW     = (const float*)d_in[17];  // (8000,1536)
    const float* pb     = (const float*)d_in[18];
    const float* c2W    = (const float*)d_in[19];  // (512,512)
    const float* c2b    = (const float*)d_in[20];
    float* out = (float*)d_out;

    float* base = nullptr;
    cudaGetSymbolAddress((void**)&base, g_scratch);
    float* preZ   = base + OFF_PREZ;
    float* preU   = base + OFF_PREU;
    float* partZ  = base + OFF_PARTZ;
    float* partU  = base + OFF_PARTU;
    float* partGI = base + OFF_PARTGI;
    float* partPJ = base + OFF_PARTPJ;
    float* scoreZ = base + OFF_SCZ;
    float* scoreU = base + OFF_SCU;
    float* scoreC = base + OFF_SCC;
    float* ctxZ   = base + OFF_CTXZ;
    float* ctxU   = base + OFF_CTXU;
    float* gin    = base + OFF_GIN;
    float* gi     = base + OFF_GI;
    float* gh     = base + OFF_GH;
    float* hnew   = base + OFF_HNEW;
    float* gencat = base + OFF_GENCAT;
    float* S      = base + OFF_S;
    float* ez     = base + OFF_EZ;
    float* mz     = base + OFF_MZ;
    float* Wihp   = base + OFF_WIHP;
    float* cs     = base + OFF_CS;

    // ---- fork ----
    cudaEventRecord(g_evRoot, 0);
    cudaStreamWaitEvent(g_s1, g_evRoot, 0);
    cudaStreamWaitEvent(g_s2, g_evRoot, 0);
    cudaStreamWaitEvent(g_s3, g_evRoot, 0);

    // ---- s2: cs = tanh(z_enc @ c2W^T + c2b)  (hnew-independent precompute) ----
    gemm_tf32<2,0><<<dim3(4, 64, 1), 256, 0, g_s2>>>(z_enc, HDIM, c2W, HDIM, 0,
                                                     c2b, nullptr, nullptr,
                                                     cs, HDIM, TZ*BATCH, HDIM, HDIM);
    cudaEventRecord(g_evCS, g_s2);

    // ---- s3: padWih, then gh = hid @ Whh^T + bhh ----
    padWih<<<(NG * GINP + 255) / 256, 256, 0, g_s3>>>(Wih, Wihp);
    gemm_tf32<0,0><<<dim3(12, 1, 1), 256, 0, g_s3>>>(hid, HDIM, Whh, HDIM, 0,
                                                     bhh, nullptr, nullptr,
                                                     gh, NG, BATCH, NG, HDIM);
    cudaEventRecord(g_evP, g_s3);

    // ---- default: Z attention chain ----
    gemm_tf32<0,0><<<dim3(4, 1, 1), 256>>>(hid, HDIM, azW, 2*HDIM, 0,
                                           azb, nullptr, nullptr,
                                           preZ, HDIM, BATCH, HDIM, HDIM);
    gemm_tf32<1,0><<<dim3(4, 64, 1), 256>>>(z_enc, HDIM, azW, 2*HDIM, HDIM,
                                            nullptr, preZ, azv,
                                            partZ, 0, TZ*BATCH, HDIM, HDIM);
    reduceN<<<(TZ * BATCH) / 256, 256>>>(partZ, scoreZ, TZ * BATCH, 4);
    softmax_ctx<<<BATCH, 128>>>(scoreZ, z_enc, ctxZ, TZ);

    // ---- s1: U attention chain ----
    gemm_tf32<0,0><<<dim3(4, 1, 1), 256, 0, g_s1>>>(hid, HDIM, auW, 2*HDIM, 0,
                                                    aub, nullptr, nullptr,
                                                    preU, HDIM, BATCH, HDIM, HDIM);
    gemm_tf32<1,0><<<dim3(4, 128, 1), 256, 0, g_s1>>>(u_enc, HDIM, auW, 2*HDIM, HDIM,
                                                      nullptr, preU, auv,
                                                      partU, 0, TU*BATCH, HDIM, HDIM);
    reduceN<<<(TU * BATCH) / 256, 256, 0, g_s1>>>(partU, scoreU, TU * BATCH, 4);
    softmax_ctx<<<BATCH, 128, 0, g_s1>>>(scoreU, u_enc, ctxU, TU);

    // ---- join U; gin; join s3; gi (splitK=8); gru ----
    cudaEventRecord(g_evU, g_s1);
    cudaStreamWaitEvent(0, g_evU, 0);
    build_gin<<<BATCH, 256>>>(mt, emb, ctxU, ctxZ, degree, gin);
    cudaStreamWaitEvent(0, g_evP, 0);
    gemm_tf32<0,0><<<dim3(12, 1, 8), 256>>>(gin, GINP, Wihp, GINP, 0,
                                            nullptr, nullptr, nullptr,
                                            partGI, NG, BATCH, NG, GINP);
    reduceK<<<(BATCH * NG + 255) / 256, 256>>>(partGI, 8, BATCH, NG, bih, gi, NG);
    gru_gate<<<(BATCH * HDIM) / 256, 256>>>(gi, gh, hid, ctxZ, ctxU, hnew, gencat,
                                            out, out_size);

    // ---- fork: proj on s1; copy chain on default ----
    cudaEventRecord(g_evG, 0);
    cudaStreamWaitEvent(g_s1, g_evG, 0);

    // s1: projection -> S[:, :V] (splitK=4)
    gemm_tf32<0,0><<<dim3(63, 1, 4), 256, 0, g_s1>>>(gencat, NG, pW, NG, 0,
                                                     nullptr, nullptr, nullptr,
                                                     partPJ, VOC, BATCH, VOC, NG);
    reduceK<<<(BATCH * VOC + 255) / 256, 256, 0, g_s1>>>(partPJ, 4, BATCH, VOC, pb, S, SLD);
    cudaEventRecord(g_evS, g_s1);

    // default: z_score matvec (needs cs + hnew) -> copy_exp -> zcopy
    cudaStreamWaitEvent(0, g_evCS, 0);
    zscore_matvec<<<(TZ * BATCH) / 8, 256>>>(cs, hnew, scoreC);
    copy_exp<<<BATCH, TZ>>>(scoreC, ez, mz);
    zcopy_kernel<<<dim3((PV / 4 + 255) / 256, BATCH), 256>>>(sp, ez, mz, S);

    // ---- join proj; final softmax ----
    cudaStreamWaitEvent(0, g_evS, 0);
    final_softmax<<<BATCH, 256>>>(S, out);
}

// round 9
// speedup vs baseline: 4.0658x; 1.0470x over previous
#include <cuda_runtime.h>
#include <math.h>
#include <stdint.h>

// ---------------- problem constants ----------------
#define BATCH 128
#define HDIM  512
#define TZ    64
#define TU    128
#define DDIM  5
#define VOC   8000
#define GINR  1541          // real gin width
#define GINP  1552          // padded to multiple of 16
#define NG    1536          // 3H
#define PV    8064          // V + TZ
#define SLD   16064         // V + PV

// ---------------- scratch offsets (floats) ----------------
#define OFF_PPZ    0                             // 8 x 128x512 preZ splitK partials
#define OFF_PPU    (OFF_PPZ + 524288)            // 8 x 128x512
#define OFF_PREZ   (OFF_PPU + 524288)            // 128x512
#define OFF_PREU   (OFF_PREZ + 65536)            // 128x512
#define OFF_PARTZ  (OFF_PREU + 65536)            // 8192*4 energy-z partials
#define OFF_PARTU  (OFF_PARTZ + 32768)           // 16384*4
#define OFF_PARTGH (OFF_PARTU + 65536)           // 4 x 128x1536
#define OFF_PARTGI (OFF_PARTGH + 786432)         // 7 x 128x1536
#define OFF_PARTPJ (OFF_PARTGI + 1376256)        // 4 x 128x8000
#define OFF_SCZ    (OFF_PARTPJ + 4096000)        // 8192
#define OFF_SCU    (OFF_SCZ + 8192)              // 16384
#define OFF_SCC    (OFF_SCU + 16384)             // 8192
#define OFF_P      (OFF_SCC + 8192)              // 128x1024  [z_ctx | u_ctx]
#define OFF_G      (OFF_P + 131072)              // 128x1024  [u_ctx | z_ctx]
#define OFF_MEMB   (OFF_G + 131072)              // 128x512
#define OFF_DEGP   (OFF_MEMB + 65536)            // 128x16
#define OFF_GI     (OFF_DEGP + 2048)             // 128x1536
#define OFF_GH     (OFF_GI + 196608)             // 128x1536
#define OFF_HNEW   (OFF_GH + 196608)             // 128x512
#define OFF_S      (OFF_HNEW + 65536)            // 128x16064
#define OFF_EZ     (OFF_S + 2056192)             // 8192
#define OFF_MZ     (OFF_EZ + 8192)               // 128
#define OFF_WIHP   (OFF_MZ + 128)                // 1536x1552
#define OFF_CS     (OFF_WIHP + 2383872)          // 8192x512
#define SCRATCH_FLOATS (OFF_CS + 4194304)

__device__ float g_scratch[SCRATCH_FLOATS];

// ---------------- helpers ----------------
__device__ __forceinline__ float ftanh(float x) {
    float e = __expf(2.f * x);
    return 1.f - __fdividef(2.f, e + 1.f);
}

__device__ __forceinline__ uint32_t f2tf32(float f) {
    uint32_t r;
    asm("cvt.rna.tf32.f32 %0, %1;" : "=r"(r) : "f"(f));
    return r;
}

__device__ __forceinline__ void mma_tf32(float* c, const uint32_t* a,
                                         uint32_t b0, uint32_t b1) {
    asm volatile(
        "mma.sync.aligned.m16n8k8.row.col.f32.tf32.tf32.f32 "
        "{%0,%1,%2,%3}, {%4,%5,%6,%7}, {%8,%9}, {%0,%1,%2,%3};"
        : "+f"(c[0]), "+f"(c[1]), "+f"(c[2]), "+f"(c[3])
        : "r"(a[0]), "r"(a[1]), "r"(a[2]), "r"(a[3]), "r"(b0), "r"(b1));
}

// ---------------- TF32 NT GEMM ----------------
// C = A(MxK, lda) @ Bw(NxK, ldb, +bofs)^T
// EPI=0: plain; splitK via gridDim.z (slice z at C + z*M*ldc, no bias);
//        if gridDim.z==1 and bias, bias added inline.
// EPI=1: fused score partials: sum_col ftanh(acc + bias + pre[b,col]) * wv,
//        b = row % BATCH; wv = PERB ? wvec[b*N+col] : wvec[col].
// EPI=2: write ftanh(acc + bias) elementwise (nz must be 1).
#define BM 128
#define BN 128
#define BK 16
#define PAD 20

template<int EPI, int PERB>
__global__ void __launch_bounds__(256, 2)
gemm_tf32(const float* __restrict__ A, int lda,
          const float* __restrict__ Bw, int ldb, int bofs,
          const float* __restrict__ bias,
          const float* __restrict__ pre,
          const float* __restrict__ wvec,
          float* __restrict__ C, int ldc,
          int M, int N, int K)
{
    __shared__ __align__(16) uint32_t As[2][BM][PAD];
    __shared__ __align__(16) uint32_t Bs[2][BN][PAD];
    __shared__ float red[BM][2];

    const int tid = threadIdx.x;
    const int lane = tid & 31, wid = tid >> 5;
    const int warpRow = wid & 3, warpCol = wid >> 2;
    const int row0 = blockIdx.y * BM, col0 = blockIdx.x * BN;

    const int nkTot = K / BK;
    const int nz = gridDim.z;
    const int kPer = (nkTot + nz - 1) / nz;
    const int kt0 = blockIdx.z * kPer;
    int kt1 = kt0 + kPer; if (kt1 > nkTot) kt1 = nkTot;

    float acc[2][8][4];
    #pragma unroll
    for (int i = 0; i < 2; i++)
        #pragma unroll
        for (int j = 0; j < 8; j++)
            #pragma unroll
            for (int l = 0; l < 4; l++) acc[i][j][l] = 0.f;

    float4 ra[2], rb[2];

    auto gload = [&](int kt) {
        const int kbase = kt * BK;
        #pragma unroll
        for (int h = 0; h < 2; h++) {
            int idx = tid + h * 256;
            int r = idx >> 2, kq = (idx & 3) << 2;
            ra[h] = *(const float4*)(A + (size_t)(row0 + r) * lda + kbase + kq);
            int cn = col0 + r;
            if (cn < N)
                rb[h] = *(const float4*)(Bw + (size_t)cn * ldb + bofs + kbase + kq);
            else
                rb[h] = make_float4(0.f, 0.f, 0.f, 0.f);
        }
    };
    auto sstore = [&](int buf) {
        #pragma unroll
        for (int h = 0; h < 2; h++) {
            int idx = tid + h * 256;
            int r = idx >> 2, kq = (idx & 3) << 2;
            uint4 ua, ub;
            ua.x = f2tf32(ra[h].x); ua.y = f2tf32(ra[h].y);
            ua.z = f2tf32(ra[h].z); ua.w = f2tf32(ra[h].w);
            ub.x = f2tf32(rb[h].x); ub.y = f2tf32(rb[h].y);
            ub.z = f2tf32(rb[h].z); ub.w = f2tf32(rb[h].w);
            *(uint4*)&As[buf][r][kq] = ua;
            *(uint4*)&Bs[buf][r][kq] = ub;
        }
    };

    gload(kt0);
    sstore(0);
    __syncthreads();

    int buf = 0;
    for (int kt = kt0; kt < kt1; kt++) {
        if (kt + 1 < kt1) gload(kt + 1);

        #pragma unroll
        for (int ks = 0; ks < 2; ks++) {
            const int k = ks * 8 + (lane & 3);
            uint32_t a[2][4];
            #pragma unroll
            for (int mi = 0; mi < 2; mi++) {
                int r = warpRow * 32 + mi * 16 + (lane >> 2);
                a[mi][0] = As[buf][r][k];
                a[mi][1] = As[buf][r + 8][k];
                a[mi][2] = As[buf][r][k + 4];
                a[mi][3] = As[buf][r + 8][k + 4];
            }
            #pragma unroll
            for (int ni = 0; ni < 8; ni++) {
                int cb = warpCol * 64 + ni * 8 + (lane >> 2);
                uint32_t b0 = Bs[buf][cb][k];
                uint32_t b1 = Bs[buf][cb][k + 4];
                #pragma unroll
                for (int mi = 0; mi < 2; mi++)
                    mma_tf32(acc[mi][ni], a[mi], b0, b1);
            }
        }

        if (kt + 1 < kt1) sstore(buf ^ 1);
        __syncthreads();
        buf ^= 1;
    }

    if (EPI != 1) {
        float* Cb = C + (size_t)blockIdx.z * ((size_t)M * ldc);
        #pragma unroll
        for (int mi = 0; mi < 2; mi++) {
            int r = row0 + warpRow * 32 + mi * 16 + (lane >> 2);
            #pragma unroll
            for (int ni = 0; ni < 8; ni++) {
                int cb = col0 + warpCol * 64 + ni * 8 + 2 * (lane & 3);
                float bs0 = (bias && cb < N)     ? bias[cb]     : 0.f;
                float bs1 = (bias && cb + 1 < N) ? bias[cb + 1] : 0.f;
                float v00 = acc[mi][ni][0] + bs0;
                float v01 = acc[mi][ni][1] + bs1;
                float v10 = acc[mi][ni][2] + bs0;
                float v11 = acc[mi][ni][3] + bs1;
                if (EPI == 2) {
                    v00 = ftanh(v00); v01 = ftanh(v01);
                    v10 = ftanh(v10); v11 = ftanh(v11);
                }
                if (cb < N)     Cb[(size_t)r * ldc + cb]           = v00;
                if (cb + 1 < N) Cb[(size_t)r * ldc + cb + 1]       = v01;
                if (cb < N)     Cb[(size_t)(r + 8) * ldc + cb]     = v10;
                if (cb + 1 < N) Cb[(size_t)(r + 8) * ldc + cb + 1] = v11;
            }
        }
    } else {
        #pragma unroll
        for (int mi = 0; mi < 2; mi++) {
            int rl = warpRow * 32 + mi * 16 + (lane >> 2);   // local row
            int bL = rl, bH = rl + 8;                        // b = row % 128
            float s0 = 0.f, s1 = 0.f;
            #pragma unroll
            for (int ni = 0; ni < 8; ni++) {
                int colL = warpCol * 64 + ni * 8 + 2 * (lane & 3);
                #pragma unroll
                for (int j = 0; j < 2; j++) {
                    int gc = col0 + colL + j;
                    float bs = bias ? bias[gc] : 0.f;
                    float e0 = acc[mi][ni][j]     + bs;
                    float e1 = acc[mi][ni][2 + j] + bs;
                    if (pre) { e0 += pre[bL * N + gc]; e1 += pre[bH * N + gc]; }
                    e0 = ftanh(e0); e1 = ftanh(e1);
                    float w0 = PERB ? wvec[bL * N + gc] : wvec[gc];
                    float w1 = PERB ? wvec[bH * N + gc] : wvec[gc];
                    s0 += e0 * w0;
                    s1 += e1 * w1;
                }
            }
            s0 += __shfl_xor_sync(0xffffffffu, s0, 1);
            s0 += __shfl_xor_sync(0xffffffffu, s0, 2);
            s1 += __shfl_xor_sync(0xffffffffu, s1, 1);
            s1 += __shfl_xor_sync(0xffffffffu, s1, 2);
            if ((lane & 3) == 0) {
                red[rl][warpCol]     = s0;
                red[rl + 8][warpCol] = s1;
            }
        }
        __syncthreads();
        if (tid < BM) {
            float s = red[tid][0] + red[tid][1];
            C[(size_t)(row0 + tid) * gridDim.x + blockIdx.x] = s;
        }
    }
}

// sum split-K slices + bias -> dst (row-major with stride ldd)
__global__ void reduceK(const float* __restrict__ part, int slices, int M, int N,
                        const float* __restrict__ bias, float* __restrict__ dst, int ldd)
{
    int i = blockIdx.x * blockDim.x + threadIdx.x;
    if (i >= M * N) return;
    int m = i / N, n = i - m * N;
    float s = bias ? bias[n] : 0.f;
    for (int z = 0; z < slices; z++) s += part[(size_t)z * M * N + i];
    dst[(size_t)m * ldd + n] = s;
}

// sum G n-block partials per row (fused-score reduce)
__global__ void reduceN(const float* __restrict__ part, float* __restrict__ out,
                        int M, int G)
{
    int m = blockIdx.x * blockDim.x + threadIdx.x;
    if (m < M) {
        float s = 0.f;
        for (int g = 0; g < G; g++) s += part[(size_t)m * G + g];
        out[m] = s;
    }
}

// pad-copy Wih (1536 x 1541) -> (1536 x 1552), zero-filled tail
__global__ void padWih(const float* __restrict__ W, float* __restrict__ Wp)
{
    int i = blockIdx.x * blockDim.x + threadIdx.x;
    if (i >= NG * GINP) return;
    int n = i / GINP, k = i - n * GINP;
    Wp[i] = (k < GINR) ? W[(size_t)n * GINR + k] : 0.f;
}

// build m_embed (128x512) and degree-pad (128x16)
__global__ void build_embdeg(const int* __restrict__ mt, const float* __restrict__ emb,
                             const float* __restrict__ degree,
                             float* __restrict__ memb, float* __restrict__ degp)
{
    int b = blockIdx.x, t = threadIdx.x;          // 128 threads
    int m = mt[b];
    ((float4*)memb)[b * 128 + t] = ((const float4*)emb)[(size_t)m * 128 + t];
    if (t < 16) degp[b * 16 + t] = (t < DDIM) ? degree[b * DDIM + t] : 0.f;
}

// per-b softmax over T scores (score[t*BATCH + b]) + context into two concat slots
__global__ void softmax_ctx(const float* __restrict__ score,
                            const float* __restrict__ enc,   // (T,B,H)
                            float* __restrict__ d1,          // + col offset, stride 1024
                            float* __restrict__ d2,          // + col offset, stride 1024
                            int T)
{
    int b = blockIdx.x, tid = threadIdx.x;        // 128 threads
    __shared__ float sw[128];
    __shared__ float red[128];

    float v = -1e30f;
    if (tid < T) { v = score[tid * BATCH + b]; }
    red[tid] = v;
    __syncthreads();
    for (int s = 64; s > 0; s >>= 1) { if (tid < s) red[tid] = fmaxf(red[tid], red[tid + s]); __syncthreads(); }
    float mx = red[0];
    __syncthreads();

    float e = 0.f;
    if (tid < T) e = __expf(v - mx);
    red[tid] = e;
    __syncthreads();
    for (int s = 64; s > 0; s >>= 1) { if (tid < s) red[tid] += red[tid + s]; __syncthreads(); }
    float inv = __fdividef(1.f, red[0]);
    __syncthreads();
    sw[tid] = e * inv;         // zero for tid >= T
    __syncthreads();

    const float4* enc4 = (const float4*)enc;
    int h4 = tid;              // 0..127
    float4 acc = make_float4(0.f, 0.f, 0.f, 0.f);
    for (int t = 0; t < T; t++) {
        float w = sw[t];
        float4 x = enc4[((size_t)t * BATCH + b) * (HDIM / 4) + h4];
        acc.x += w * x.x; acc.y += w * x.y; acc.z += w * x.z; acc.w += w * x.w;
    }
    ((float4*)(d1 + (size_t)b * 1024))[h4] = acc;
    ((float4*)(d2 + (size_t)b * 1024))[h4] = acc;
}

// z_score matvec: scoreC[r] = dot(cs[r,:], hnew[r%128,:]);  r = t*BATCH + b
__global__ void zscore_matvec(const float* __restrict__ cs,
                              const float* __restrict__ hnew,
                              float* __restrict__ scoreC)
{
    int w = threadIdx.x >> 5, lane = threadIdx.x & 31;
    int r = blockIdx.x * 8 + w;
    int b = r & (BATCH - 1);
    const float4* crow = (const float4*)(cs + (size_t)r * HDIM);
    const float4* hrow = (const float4*)(hnew + (size_t)b * HDIM);
    float acc = 0.f;
    #pragma unroll
    for (int q = 0; q < 4; q++) {
        float4 c = crow[lane + 32 * q];
        float4 h = hrow[lane + 32 * q];
        acc += c.x * h.x + c.y * h.y + c.z * h.z + c.w * h.w;
    }
    #pragma unroll
    for (int s = 16; s > 0; s >>= 1) acc += __shfl_xor_sync(0xffffffffu, acc, s);
    if (lane == 0) scoreC[r] = acc;
}

// copy-score: per-b max + exp (unnormalized)
__global__ void copy_exp(const float* __restrict__ score,
                         float* __restrict__ ez, float* __restrict__ mz)
{
    int b = blockIdx.x, t = threadIdx.x;          // 64 threads
    __shared__ float sv[64];
    __shared__ float red[64];
    float v = score[t * BATCH + b];
    sv[t] = v; red[t] = v;
    __syncthreads();
    for (int s = 32; s > 0; s >>= 1) { if (t < s) red[t] = fmaxf(red[t], red[t + s]); __syncthreads(); }
    float mx = red[0];
    ez[b * TZ + t] = __expf(sv[t] - mx);
    if (t == 0) mz[b] = mx;
}

// z_copy = log(sum_t e[b,t] * sparse[b,t,v]) + m[b] -> S cols [VOC, VOC+PV)
__global__ void zcopy_kernel(const float* __restrict__ sp,
                             const float* __restrict__ ez,
                             const float* __restrict__ mz,
                             float* __restrict__ S)
{
    int b = blockIdx.y;
    int v4 = blockIdx.x * blockDim.x + threadIdx.x;
    __shared__ float e[TZ];
    if (threadIdx.x < TZ) e[threadIdx.x] = ez[b * TZ + threadIdx.x];
    __syncthreads();
    if (v4 < PV / 4) {
        const float4* row = (const float4*)(sp + (size_t)b * TZ * PV) + v4;
        float4 acc = make_float4(0.f, 0.f, 0.f, 0.f);
        #pragma unroll 8
        for (int t = 0; t < TZ; t++) {
            float w = e[t];
            float4 x = row[(size_t)t * (PV / 4)];
            acc.x += w * x.x; acc.y += w * x.y; acc.z += w * x.z; acc.w += w * x.w;
        }
        float m = mz[b];
        float* dst = S + (size_t)b * SLD + VOC + 4 * v4;
        dst[0] = __logf(acc.x) + m;
        dst[1] = __logf(acc.y) + m;
        dst[2] = __logf(acc.z) + m;
        dst[3] = __logf(acc.w) + m;
    }
}

// GRU gates -> h_new; write gru_out (x2) into out tail
__global__ void gru_gate(const float* __restrict__ gi, const float* __restrict__ gh,
                         const float* __restrict__ hprev,
                         float* __restrict__ hnew,
                         float* __restrict__ out, int out_size)
{
    int idx = blockIdx.x * blockDim.x + threadIdx.x;
    if (idx >= BATCH * HDIM) return;
    int b = idx >> 9, j = idx & 511;
    const float* gib = gi + (size_t)b * NG;
    const float* ghb = gh + (size_t)b * NG;
    float r = __fdividef(1.f, 1.f + __expf(-(gib[j]       + ghb[j])));
    float z = __fdividef(1.f, 1.f + __expf(-(gib[512 + j] + ghb[512 + j])));
    float n = ftanh(gib[1024 + j] + r * ghb[1024 + j]);
    float h = (1.f - z) * n + z * hprev[idx];
    hnew[idx] = h;
    const int base = BATCH * PV;
    if (out_size >= base + BATCH * HDIM)     out[base + idx] = h;
    if (out_size >= base + 2 * BATCH * HDIM) out[base + BATCH * HDIM + idx] = h;
}

// final softmax over SLD -> proba = [gen + cp[:, :V] | cp[:, V:]]
__global__ void final_softmax(const float* __restrict__ S, float* __restrict__ out)
{
    int b = blockIdx.x, tid = threadIdx.x;        // 256 threads
    __shared__ float red[256];
    const float4* row4 = (const float4*)(S + (size_t)b * SLD);
    const int n4 = SLD / 4;

    float mx = -1e30f;
    for (int i = tid; i < n4; i += 256) {
        float4 x = row4[i];
        mx = fmaxf(mx, fmaxf(fmaxf(x.x, x.y), fmaxf(x.z, x.w)));
    }
    red[tid] = mx;
    __syncthreads();
    for (int s = 128; s > 0; s >>= 1) { if (tid < s) red[tid] = fmaxf(red[tid], red[tid + s]); __syncthreads(); }
    mx = red[0];
    __syncthreads();

    float sm = 0.f;
    for (int i = tid; i < n4; i += 256) {
        float4 x = row4[i];
        sm += __expf(x.x - mx) + __expf(x.y - mx) + __expf(x.z - mx) + __expf(x.w - mx);
    }
    red[tid] = sm;
    __syncthreads();
    for (int s = 128; s > 0; s >>= 1) { if (tid < s) red[tid] += red[tid + s]; __syncthreads(); }
    float inv = __fdividef(1.f, red[0]);

    const float4* cp4 = (const float4*)(S + (size_t)b * SLD + VOC);
    float4* out4 = (float4*)(out + (size_t)b * PV);
    for (int i = tid; i < PV / 4; i += 256) {
        float4 c = cp4[i];
        float4 o;
        o.x = __expf(c.x - mx) * inv;
        o.y = __expf(c.y - mx) * inv;
        o.z = __expf(c.z - mx) * inv;
        o.w = __expf(c.w - mx) * inv;
        if (i < VOC / 4) {
            float4 g = row4[i];
            o.x += __expf(g.x - mx) * inv;
            o.y += __expf(g.y - mx) * inv;
            o.z += __expf(g.z - mx) * inv;
            o.w += __expf(g.w - mx) * inv;
        }
        out4[i] = o;
    }
}

// ---------------------------------------------------------------------------
static cudaStream_t g_s1, g_s2, g_s3;
static cudaEvent_t g_evRoot, g_evPreU, g_evCS, g_evZ, g_evU, g_evGH, g_evG, g_evS;
static bool g_init = false;

extern "C" void kernel_launch(void* const* d_in, const int* in_sizes, int n_in,
                              void* d_out, int out_size)
{
    if (!g_init) {
        cudaStreamCreateWithFlags(&g_s1, cudaStreamNonBlocking);
        cudaStreamCreateWithFlags(&g_s2, cudaStreamNonBlocking);
        cudaStreamCreateWithFlags(&g_s3, cudaStreamNonBlocking);
        cudaEventCreateWithFlags(&g_evRoot, cudaEventDisableTiming);
        cudaEventCreateWithFlags(&g_evPreU, cudaEventDisableTiming);
        cudaEventCreateWithFlags(&g_evCS,   cudaEventDisableTiming);
        cudaEventCreateWithFlags(&g_evZ,    cudaEventDisableTiming);
        cudaEventCreateWithFlags(&g_evU,    cudaEventDisableTiming);
        cudaEventCreateWithFlags(&g_evGH,   cudaEventDisableTiming);
        cudaEventCreateWithFlags(&g_evG,    cudaEventDisableTiming);
        cudaEventCreateWithFlags(&g_evS,    cudaEventDisableTiming);
        g_init = true;
    }

    const float* z_enc  = (const float*)d_in[0];
    const float* u_enc  = (const float*)d_in[1];
    const int*   mt     = (const int*)d_in[2];
    const float* degree = (const float*)d_in[3];
    const float* hid    = (const float*)d_in[4];
    const float* sp     = (const float*)d_in[5];
    const float* emb    = (const float*)d_in[6];
    const float* azW    = (const float*)d_in[7];
    const float* azb    = (const float*)d_in[8];
    const float* azv    = (const float*)d_in[9];
    const float* auW    = (const float*)d_in[10];
    const float* aub    = (const float*)d_in[11];
    const float* auv    = (const float*)d_in[12];
    const float* Wih    = (const float*)d_in[13];
    const float* Whh    = (const float*)d_in[14];
    const float* bih    = (const float*)d_in[15];
    const float* bhh    = (const float*)d_in[16];
    const float* pW     = (const float*)d_in[17];
    const float* pb     = (const float*)d_in[18];
    const float* c2W    = (const float*)d_in[19];
    const float* c2b    = (const float*)d_in[20];
    float* out = (float*)d_out;

    float* base = nullptr;
    cudaGetSymbolAddress((void**)&base, g_scratch);
    float* ppz    = base + OFF_PPZ;
    float* ppu    = base + OFF_PPU;
    float* preZ   = base + OFF_PREZ;
    float* preU   = base + OFF_PREU;
    float* partZ  = base + OFF_PARTZ;
    float* partU  = base + OFF_PARTU;
    float* partGH = base + OFF_PARTGH;
    float* partGI = base + OFF_PARTGI;
    float* partPJ = base + OFF_PARTPJ;
    float* scoreZ = base + OFF_SCZ;
    float* scoreU = base + OFF_SCU;
    float* scoreC = base + OFF_SCC;
    float* P      = base + OFF_P;      // [z_ctx | u_ctx]
    float* G      = base + OFF_G;      // [u_ctx | z_ctx]
    float* memb   = base + OFF_MEMB;
    float* degp   = base + OFF_DEGP;
    float* gi     = base + OFF_GI;
    float* gh     = base + OFF_GH;
    float* hnew   = base + OFF_HNEW;
    float* S      = base + OFF_S;
    float* ez     = base + OFF_EZ;
    float* mz     = base + OFF_MZ;
    float* Wihp   = base + OFF_WIHP;
    float* cs     = base + OFF_CS;

    // ---- fork ----
    cudaEventRecord(g_evRoot, 0);
    cudaStreamWaitEvent(g_s1, g_evRoot, 0);
    cudaStreamWaitEvent(g_s2, g_evRoot, 0);
    cudaStreamWaitEvent(g_s3, g_evRoot, 0);

    // ---- s3 (t=0 chain): padWih, embed/deg build, gi0 + gi2, gh ----
    padWih<<<(NG * GINP + 255) / 256, 256, 0, g_s3>>>(Wih, Wihp);
    build_embdeg<<<BATCH, 128, 0, g_s3>>>(mt, emb, degree, memb, degp);
    // gi0: m_embed part (gin cols 0..512) -> partGI slices 0,1
    gemm_tf32<0,0><<<dim3(12, 1, 2), 256, 0, g_s3>>>(memb, HDIM, Wihp, GINP, 0,
                                                     nullptr, nullptr, nullptr,
                                                     partGI, NG, BATCH, NG, HDIM);
    // gi2: degree part (gin cols 1536..1552) -> partGI slice 2
    gemm_tf32<0,0><<<dim3(12, 1, 1), 256, 0, g_s3>>>(degp, 16, Wihp, GINP, 1536,
                                                     nullptr, nullptr, nullptr,
                                                     partGI + 2 * (size_t)BATCH * NG,
                                                     NG, BATCH, NG, 16);
    // gh = hid @ Whh^T + bhh (splitK 4)
    gemm_tf32<0,0><<<dim3(12, 1, 4), 256, 0, g_s3>>>(hid, HDIM, Whh, HDIM, 0,
                                                     nullptr, nullptr, nullptr,
                                                     partGH, NG, BATCH, NG, HDIM);
    reduceK<<<(BATCH * NG + 255) / 256, 256, 0, g_s3>>>(partGH, 4, BATCH, NG, bhh, gh, NG);
    cudaEventRecord(g_evGH, g_s3);

    // ---- default: Z attention chain ----
    gemm_tf32<0,0><<<dim3(4, 1, 8), 256>>>(hid, HDIM, azW, 2*HDIM, 0,
                                           nullptr, nullptr, nullptr,
                                           ppz, HDIM, BATCH, HDIM, HDIM);
    reduceK<<<(BATCH * HDIM + 255) / 256, 256>>>(ppz, 8, BATCH, HDIM, azb, preZ, HDIM);
    gemm_tf32<1,0><<<dim3(4, 64, 1), 256>>>(z_enc, HDIM, azW, 2*HDIM, HDIM,
                                            nullptr, preZ, azv,
                                            partZ, 0, TZ*BATCH, HDIM, HDIM);
    reduceN<<<(TZ * BATCH) / 256, 256>>>(partZ, scoreZ, TZ * BATCH, 4);
    softmax_ctx<<<BATCH, 128>>>(scoreZ, z_enc, P /*z at cols 0*/, G + 512, TZ);
    cudaEventRecord(g_evZ, 0);

    // ---- s1: U attention chain ----
    gemm_tf32<0,0><<<dim3(4, 1, 8), 256, 0, g_s1>>>(hid, HDIM, auW, 2*HDIM, 0,
                                                    nullptr, nullptr, nullptr,
                                                    ppu, HDIM, BATCH, HDIM, HDIM);
    reduceK<<<(BATCH * HDIM + 255) / 256, 256, 0, g_s1>>>(ppu, 8, BATCH, HDIM, aub, preU, HDIM);
    cudaEventRecord(g_evPreU, g_s1);
    gemm_tf32<1,0><<<dim3(4, 128, 1), 256, 0, g_s1>>>(u_enc, HDIM, auW, 2*HDIM, HDIM,
                                                      nullptr, preU, auv,
                                                      partU, 0, TU*BATCH, HDIM, HDIM);
    reduceN<<<(TU * BATCH) / 256, 256, 0, g_s1>>>(partU, scoreU, TU * BATCH, 4);
    softmax_ctx<<<BATCH, 128, 0, g_s1>>>(scoreU, u_enc, P + 512, G /*u at cols 0*/, TU);
    cudaEventRecord(g_evU, g_s1);

    // ---- s2: cs precompute (starts after preU so energy GEMMs get SMs first) ----
    cudaStreamWaitEvent(g_s2, g_evPreU, 0);
    gemm_tf32<2,0><<<dim3(4, 64, 1), 256, 0, g_s2>>>(z_enc, HDIM, c2W, HDIM, 0,
                                                     c2b, nullptr, nullptr,
                                                     cs, HDIM, TZ*BATCH, HDIM, HDIM);
    cudaEventRecord(g_evCS, g_s2);

    // ---- default: gi1 (ctx part) -> reduce -> gru ----
    cudaStreamWaitEvent(0, g_evU, 0);
    gemm_tf32<0,0><<<dim3(12, 1, 4), 256>>>(G, 1024, Wihp, GINP, 512,
                                            nullptr, nullptr, nullptr,
                                            partGI + 3 * (size_t)BATCH * NG,
                                            NG, BATCH, NG, 1024);
    reduceK<<<(BATCH * NG + 255) / 256, 256>>>(partGI, 7, BATCH, NG, bih, gi, NG);
    cudaStreamWaitEvent(0, g_evGH, 0);
    gru_gate<<<(BATCH * HDIM) / 256, 256>>>(gi, gh, hid, hnew, out, out_size);
    cudaEventRecord(g_evG, 0);

    // ---- s1: proj1 (ctx part, pre-gru) then proj2 (hnew part) ----
    cudaStreamWaitEvent(g_s1, g_evZ, 0);
    gemm_tf32<0,0><<<dim3(63, 1, 2), 256, 0, g_s1>>>(P, 1024, pW, NG, 0,
                                                     nullptr, nullptr, nullptr,
                                                     partPJ, VOC, BATCH, VOC, 1024);
    cudaStreamWaitEvent(g_s1, g_evG, 0);
    gemm_tf32<0,0><<<dim3(63, 1, 2), 256, 0, g_s1>>>(hnew, HDIM, pW, NG, 1024,
                                                     nullptr, nullptr, nullptr,
                                                     partPJ + 2 * (size_t)BATCH * VOC,
                                                     VOC, BATCH, VOC, HDIM);
    reduceK<<<(BATCH * VOC + 255) / 256, 256, 0, g_s1>>>(partPJ, 4, BATCH, VOC, pb, S, SLD);
    cudaEventRecord(g_evS, g_s1);

    // ---- default: z_score matvec -> copy_exp -> zcopy ----
    cudaStreamWaitEvent(0, g_evCS, 0);
    zscore_matvec<<<(TZ * BATCH) / 8, 256>>>(cs, hnew, scoreC);
    copy_exp<<<BATCH, TZ>>>(scoreC, ez, mz);
    zcopy_kernel<<<dim3((PV / 4 + 255) / 256, BATCH), 256>>>(sp, ez, mz, S);

    // ---- join proj; final softmax ----
    cudaStreamWaitEvent(0, g_evS, 0);
    final_softmax<<<BATCH, 256>>>(S, out);
}